// round 10
// baseline (speedup 1.0000x reference)
#include <cuda_runtime.h>
#include <cuda_fp16.h>
#include <math.h>
#include <stdint.h>

#define NB 4
#define NS 2048
#define ND 1024
#define NH 4096
#define NE 8
#define NTOK (NB*NS)      /* 8192 tokens */
#define NPAIR (NTOK*2)    /* 16384 (token,expert) pairs */

#define TM 128
#define TN 256
#define KC 64               /* K per stage (64 halfs = 128 B rows) */
#define NSTG 3
#define ROWB 144            /* padded row: 128 B data + 16 B pad */
#define ABYTES (128*ROWB)   /* A tile per stage: 18432 B */
#define BBYTES (256*ROWB)   /* B tile per stage: 36864 B */
#define STGB (ABYTES+BBYTES)
#define SOFF 512
#define DSMEM (SOFF + NSTG*STGB)   /* 166400 B -> 1 CTA/SM */

#define NTHR 256            /* 8 warps, 2x4 grid, 64x64 warptiles */

// ---------------- device scratch (static allocations only) ----------------
__device__ float g_M[ND*NE];
__device__ float g_cvec[NE];
__device__ float g_qv[NE];
__device__ int   g_cnt[NE];
__device__ int   g_list[NE][NTOK];
__device__ float g_gate[NPAIR];
__device__ __half g_xh[(size_t)NTOK*ND];      // fp16 x (written by router)
__device__ __half g_W1t[(size_t)NE*NH*ND];    // W1^T  [e][n][k], fp16
__device__ __half g_W2t[(size_t)NE*ND*NH];    // W2^T  [e][n][k], fp16
__device__ __half g_h[(size_t)NPAIR*NH];      // hidden acts, fp16
__device__ float g_y[(size_t)NPAIR*ND];       // per-pair outputs, fp32
__device__ float g_imp[NE];
__device__ float g_rz;
__device__ float g_ent;

// ---------------- helpers ----------------
__device__ __forceinline__ uint32_t smem_u32(const void* p) {
    uint32_t a;
    asm("{ .reg .u64 t; cvta.to.shared.u64 t, %1; cvt.u32.u64 %0, t; }"
        : "=r"(a) : "l"(p));
    return a;
}
__device__ __forceinline__ void cp16(uint32_t dst, const void* src, uint32_t bytes) {
    asm volatile("cp.async.cg.shared.global [%0], [%1], 16, %2;\n"
                 :: "r"(dst), "l"(src), "r"(bytes) : "memory");
}
#define CP_COMMIT() asm volatile("cp.async.commit_group;\n" ::: "memory")
#define CP_WAIT1()  asm volatile("cp.async.wait_group 1;\n" ::: "memory")
#define CP_WAIT0()  asm volatile("cp.async.wait_group 0;\n" ::: "memory")

__device__ __forceinline__ void mma_f16(float* c, const uint32_t* a, const uint32_t* b) {
    asm volatile("mma.sync.aligned.m16n8k16.row.col.f32.f16.f16.f32 "
        "{%0,%1,%2,%3}, {%4,%5,%6,%7}, {%8,%9}, {%0,%1,%2,%3};"
        : "+f"(c[0]), "+f"(c[1]), "+f"(c[2]), "+f"(c[3])
        : "r"(a[0]), "r"(a[1]), "r"(a[2]), "r"(a[3]), "r"(b[0]), "r"(b[1]));
}
__device__ __forceinline__ void ldsm4(uint32_t* r, uint32_t a) {
    asm volatile("ldmatrix.sync.aligned.m8n8.x4.shared.b16 {%0,%1,%2,%3}, [%4];"
        : "=r"(r[0]), "=r"(r[1]), "=r"(r[2]), "=r"(r[3]) : "r"(a));
}

// ---------------- fused prep ----------------
__device__ __forceinline__ float blk_sum(float v, float* sred) {
    int tid = threadIdx.x;
    sred[tid] = v;
    __syncthreads();
    #pragma unroll
    for (int o = 128; o > 0; o >>= 1) {
        if (tid < o) sred[tid] += sred[tid + o];
        __syncthreads();
    }
    float r = sred[0];
    __syncthreads();
    return r;
}

__global__ __launch_bounds__(256) void prep_all(
        const float* __restrict__ ctx_W, const float* __restrict__ r_W,
        const float* __restrict__ ctx_b, const float* __restrict__ q_W,
        const float* __restrict__ q_b,  const float* __restrict__ r_b) {
    __shared__ float sred[256];
    int tid = threadIdx.x;
    if (blockIdx.x == 0) {
        if (tid < NE) { g_cnt[tid] = 0; g_imp[tid] = 0.f; }
        if (tid == 0) { g_rz = 0.f; g_ent = 0.f; }
        float pc[NE], pq[NE];
        #pragma unroll
        for (int e = 0; e < NE; e++) { pc[e] = 0.f; pq[e] = 0.f; }
        for (int d = tid; d < ND; d += 256) {
            float cb = ctx_b[d] + q_b[d];
            float qw = q_W[d];
            #pragma unroll
            for (int e = 0; e < NE; e++) {
                pc[e] += cb * r_W[d*NE + e];
                pq[e] += qw * r_W[d*NE + e];
            }
        }
        #pragma unroll
        for (int e = 0; e < NE; e++) {
            float vc = blk_sum(pc[e], sred);
            float vq = blk_sum(pq[e], sred);
            if (tid == 0) { g_cvec[e] = vc + r_b[e]; g_qv[e] = vq; }
        }
    } else {
        int j = blockIdx.x - 1;
        float part[NE];
        #pragma unroll
        for (int e = 0; e < NE; e++) part[e] = 0.f;
        for (int d = tid; d < ND; d += 256) {
            float w = ctx_W[(size_t)j*ND + d];
            #pragma unroll
            for (int e = 0; e < NE; e++) part[e] += w * r_W[d*NE + e];
        }
        #pragma unroll
        for (int e = 0; e < NE; e++) {
            float v = blk_sum(part[e], sred);
            if (tid == 0) g_M[j*NE + e] = v;
        }
    }
}

// ---------------- transpose + fp16 ----------------
__global__ void transpose_h(const float* __restrict__ S, int R, int C, int which) {
    __shared__ float t[32][33];
    __half* D = which ? g_W2t : g_W1t;
    int e = blockIdx.z;
    S += (size_t)e*R*C; D += (size_t)e*R*C;
    int c0 = blockIdx.x*32, r0 = blockIdx.y*32;
    int tx = threadIdx.x, ty = threadIdx.y;
    #pragma unroll
    for (int i = 0; i < 32; i += 8)
        t[ty+i][tx] = S[(size_t)(r0+ty+i)*C + c0+tx];
    __syncthreads();
    #pragma unroll
    for (int i = 0; i < 32; i += 8)
        D[(size_t)(c0+ty+i)*R + r0+tx] = __float2half(t[tx][ty+i]);
}

// ---------------- router: one warp per token ----------------
__global__ __launch_bounds__(256) void router_kernel(
        const float* __restrict__ x, const float* __restrict__ ctx,
        const float* __restrict__ quality,
        const float* __restrict__ rn_g, const float* __restrict__ rn_b,
        const float* __restrict__ cn_g, const float* __restrict__ cn_b,
        const float* __restrict__ r_W, const float* __restrict__ temp_p) {
    int wid = threadIdx.x >> 5, lane = threadIdx.x & 31;
    int t = blockIdx.x*8 + wid;

    const float4* xr = (const float4*)(x   + (size_t)t*ND);
    const float4* cr = (const float4*)(ctx + (size_t)t*ND);
    float4 xv[8], cv[8];
    #pragma unroll
    for (int i = 0; i < 8; i++) { xv[i] = xr[lane + 32*i]; cv[i] = cr[lane + 32*i]; }

    #pragma unroll
    for (int i = 0; i < 8; i++) {
        __half2 h0 = __floats2half2_rn(xv[i].x, xv[i].y);
        __half2 h1 = __floats2half2_rn(xv[i].z, xv[i].w);
        uint2 o = make_uint2(*(uint32_t*)&h0, *(uint32_t*)&h1);
        *(uint2*)(g_xh + (size_t)t*ND + (lane + 32*i)*4) = o;
    }

    float sx=0.f, sxx=0.f, sc=0.f, scc=0.f;
    #pragma unroll
    for (int i = 0; i < 8; i++) {
        sx  += xv[i].x + xv[i].y + xv[i].z + xv[i].w;
        sxx += xv[i].x*xv[i].x + xv[i].y*xv[i].y + xv[i].z*xv[i].z + xv[i].w*xv[i].w;
        sc  += cv[i].x + cv[i].y + cv[i].z + cv[i].w;
        scc += cv[i].x*cv[i].x + cv[i].y*cv[i].y + cv[i].z*cv[i].z + cv[i].w*cv[i].w;
    }
    #pragma unroll
    for (int o = 16; o; o >>= 1) {
        sx  += __shfl_xor_sync(0xFFFFFFFFu, sx,  o);
        sxx += __shfl_xor_sync(0xFFFFFFFFu, sxx, o);
        sc  += __shfl_xor_sync(0xFFFFFFFFu, sc,  o);
        scc += __shfl_xor_sync(0xFFFFFFFFu, scc, o);
    }
    float mu_x = sx*(1.f/ND), mu_c = sc*(1.f/ND);
    float rs_x = rsqrtf(sxx*(1.f/ND) - mu_x*mu_x + 1e-5f);
    float rs_c = rsqrtf(scc*(1.f/ND) - mu_c*mu_c + 1e-5f);

    float part[NE];
    #pragma unroll
    for (int e = 0; e < NE; e++) part[e] = 0.f;
    #pragma unroll
    for (int i = 0; i < 8; i++) {
        float xa[4] = {xv[i].x, xv[i].y, xv[i].z, xv[i].w};
        float ca[4] = {cv[i].x, cv[i].y, cv[i].z, cv[i].w};
        #pragma unroll
        for (int j = 0; j < 4; j++) {
            int d = (lane + 32*i)*4 + j;
            float nx = (xa[j]-mu_x)*rs_x*rn_g[d] + rn_b[d];
            float nc = (ca[j]-mu_c)*rs_c*cn_g[d] + cn_b[d];
            const float* rw = r_W + d*NE;
            const float* mm = g_M + d*NE;
            #pragma unroll
            for (int e = 0; e < NE; e++) part[e] += nx*rw[e] + nc*mm[e];
        }
    }
    #pragma unroll
    for (int e = 0; e < NE; e++)
        #pragma unroll
        for (int o = 16; o; o >>= 1)
            part[e] += __shfl_xor_sync(0xFFFFFFFFu, part[e], o);

    __shared__ float simp[8][NE];
    __shared__ float srz[8];
    __shared__ float sent[8];

    if (lane == 0) {
        float temp = fmaxf(temp_p[0], 0.25f);
        float q = quality[t / NS];
        float lg[NE];
        #pragma unroll
        for (int e = 0; e < NE; e++)
            lg[e] = (part[e] + g_cvec[e] + q*g_qv[e]) / temp;

        int i1 = 0;
        #pragma unroll
        for (int e = 1; e < NE; e++) if (lg[e] > lg[i1]) i1 = e;
        int i2 = (i1 == 0) ? 1 : 0;
        #pragma unroll
        for (int e = 0; e < NE; e++) {
            if (e == i1 || e == i2) continue;
            if (lg[e] > lg[i2]) i2 = e;
        }

        float mx = lg[0];
        #pragma unroll
        for (int e = 1; e < NE; e++) mx = fmaxf(mx, lg[e]);
        float se = 0.f;
        #pragma unroll
        for (int e = 0; e < NE; e++) se += expf(lg[e]-mx);
        float lse = mx + logf(se);
        float inv_se = 1.f/se;
        float ent = 0.f;
        #pragma unroll
        for (int e = 0; e < NE; e++) {
            float p = expf(lg[e]-mx)*inv_se;
            simp[wid][e] = p;
            ent -= p * (lg[e]-lse);
        }
        srz[wid]  = lse*lse;
        sent[wid] = ent;

        float ex = expf(lg[i2]-lg[i1]);
        float inv = 1.f/(1.f+ex);
        g_gate[2*t]   = inv;
        g_gate[2*t+1] = ex*inv;
        int p1 = atomicAdd(&g_cnt[i1], 1);
        g_list[i1][p1] = 2*t;
        int p2 = atomicAdd(&g_cnt[i2], 1);
        g_list[i2][p2] = 2*t+1;
    }
    __syncthreads();
    int tid = threadIdx.x;
    if (tid < NE) {
        float s = 0.f;
        #pragma unroll
        for (int w = 0; w < 8; w++) s += simp[w][tid];
        atomicAdd(&g_imp[tid], s);
    } else if (tid == 8) {
        float s = 0.f;
        #pragma unroll
        for (int w = 0; w < 8; w++) s += srz[w];
        atomicAdd(&g_rz, s);
    } else if (tid == 9) {
        float s = 0.f;
        #pragma unroll
        for (int w = 0; w < 8; w++) s += sent[w];
        atomicAdd(&g_ent, s);
    }
}

// ---------------- stage loaders ----------------
// A tile: 128 rows (gathered). B tile: 256 rows. 256 threads.
__device__ __forceinline__ void g1_load(uint32_t ab, int s,
        const __half* __restrict__ Bp, const int* rowpr, int tid) {
    int buf = s % NSTG;
    int k0 = s * KC;
    uint32_t abase = ab + buf*STGB;
    uint32_t bbase = abase + ABYTES;
    #pragma unroll
    for (int i = 0; i < 4; i++) {
        int u = tid + 256*i; int r = u >> 3, sj = u & 7;
        int pr = rowpr[r];
        const __half* src = (pr >= 0) ? (g_xh + ((size_t)(pr >> 1))*ND + k0 + sj*8) : g_xh;
        cp16(abase + r*ROWB + sj*16, src, (pr >= 0) ? 16u : 0u);
    }
    #pragma unroll
    for (int i = 0; i < 8; i++) {
        int u = tid + 256*i; int r = u >> 3, sj = u & 7;
        cp16(bbase + r*ROWB + sj*16, Bp + (size_t)r*ND + k0 + sj*8, 16u);
    }
    CP_COMMIT();
}

__device__ __forceinline__ void g2_load(uint32_t ab, int s,
        int base_m, int nvalid, const __half* __restrict__ Bp, int tid) {
    int buf = s % NSTG;
    int k0 = s * KC;
    uint32_t abase = ab + buf*STGB;
    uint32_t bbase = abase + ABYTES;
    #pragma unroll
    for (int i = 0; i < 4; i++) {
        int u = tid + 256*i; int r = u >> 3, sj = u & 7;
        bool ok = (r < nvalid);
        const __half* src = g_h + (size_t)(base_m + (ok ? r : 0))*NH + k0 + sj*8;
        cp16(abase + r*ROWB + sj*16, src, ok ? 16u : 0u);
    }
    #pragma unroll
    for (int i = 0; i < 8; i++) {
        int u = tid + 256*i; int r = u >> 3, sj = u & 7;
        cp16(bbase + r*ROWB + sj*16, Bp + (size_t)r*NH + k0 + sj*8, 16u);
    }
    CP_COMMIT();
}

// ---------------- chunk compute: 8 warps x (64x64), fp16 K=64, ldmatrix ----------------
// Per k16-step: 8 LDSM.x4 (4 A + 4 B) feed 32 HMMA -> 128 B smem per HMMA.
__device__ __forceinline__ void chunk_mma(uint32_t ab, int buf,
        int wm, int wn, int lane, float acc[4][8][4]) {
    uint32_t As = ab + buf*STGB;
    uint32_t Bs = As + ABYTES;
    int l7 = lane & 7;
    int arow = wm*64 + ((lane>>3)&1)*8 + l7;
    uint32_t acol = (uint32_t)((lane>>4)*16);
    int brow = wn*64 + ((lane>>4)&1)*8 + l7;
    uint32_t bcol = (uint32_t)(((lane>>3)&1)*16);
    #pragma unroll
    for (int ks = 0; ks < 4; ks++) {
        uint32_t kb = ks*32;
        uint32_t af[4][4], bregs[4][4];
        #pragma unroll
        for (int mt = 0; mt < 4; mt++)
            ldsm4(af[mt], As + (uint32_t)(arow + mt*16)*ROWB + kb + acol);
        #pragma unroll
        for (int p = 0; p < 4; p++)
            ldsm4(bregs[p], Bs + (uint32_t)(brow + p*16)*ROWB + kb + bcol);
        #pragma unroll
        for (int mt = 0; mt < 4; mt++)
            #pragma unroll
            for (int nt = 0; nt < 8; nt++)
                mma_f16(acc[mt][nt], af[mt], &bregs[nt>>1][(nt&1)*2]);
    }
}

// ---------------- expert offset ----------------
__device__ __forceinline__ int expert_off(int e) {
    int s = 0;
    #pragma unroll
    for (int k = 0; k < NE; k++) if (k < e) s += g_cnt[k];
    return s;
}

// ---------------- GEMM1: h = h16(gelu(x @ W1 + b1)) ----------------
__global__ __launch_bounds__(NTHR, 1) void gemm1_mma(const float* __restrict__ b1) {
    extern __shared__ char smem[];
    int e = blockIdx.z;
    int cnt = g_cnt[e];
    int m0 = blockIdx.y * TM;
    if (m0 >= cnt) return;
    int n0 = blockIdx.x * TN;
    int tid = threadIdx.x;
    int lane = tid & 31;
    int wid = tid >> 5;
    int wm = wid >> 2, wn = wid & 3;
    uint32_t ab = smem_u32(smem) + SOFF;
    int* rowpr = (int*)smem;
    __shared__ int s_base;
    if (tid < TM) {
        int m = m0 + tid;
        rowpr[tid] = (m < cnt) ? g_list[e][m] : -1;
    }
    if (tid == 0) s_base = expert_off(e) + m0;
    __syncthreads();

    const __half* Bp = g_W1t + ((size_t)e*NH + (size_t)n0)*ND;
    const int T = ND / KC;  // 16

    float acc[4][8][4];
    #pragma unroll
    for (int a = 0; a < 4; a++)
        #pragma unroll
        for (int b = 0; b < 8; b++)
            #pragma unroll
            for (int c = 0; c < 4; c++) acc[a][b][c] = 0.f;

    for (int s = 0; s < NSTG-1; s++) g1_load(ab, s, Bp, rowpr, tid);

    for (int t = 0; t < T; t++) {
        if (t < T-1) CP_WAIT1(); else CP_WAIT0();
        __syncthreads();
        if (t + NSTG - 1 < T) g1_load(ab, t + NSTG - 1, Bp, rowpr, tid);
        chunk_mma(ab, t % NSTG, wm, wn, lane, acc);
    }

    int base_m = s_base;
    const float* bb = b1 + (size_t)e*NH + n0;
    #pragma unroll
    for (int mt = 0; mt < 4; mt++) {
        int r0 = wm*64 + mt*16 + (lane >> 2);
        #pragma unroll
        for (int half = 0; half < 2; half++) {
            int r = r0 + half*8;
            int pr = rowpr[r];
            if (pr < 0) continue;
            __half* hp = g_h + (size_t)(base_m + r)*NH + n0;
            #pragma unroll
            for (int nt = 0; nt < 8; nt++) {
                int cc = wn*64 + nt*8 + 2*(lane & 3);
                float v0 = acc[mt][nt][half*2+0] + bb[cc];
                float v1 = acc[mt][nt][half*2+1] + bb[cc+1];
                __half2 o = __floats2half2_rn(v0 * normcdff(v0), v1 * normcdff(v1));
                *(__half2*)(hp + cc) = o;
            }
        }
    }
}

// ---------------- GEMM2: y = h @ W2 + b2 ----------------
__global__ __launch_bounds__(NTHR, 1) void gemm2_mma(const float* __restrict__ b2) {
    extern __shared__ char smem[];
    int e = blockIdx.z;
    int cnt = g_cnt[e];
    int m0 = blockIdx.y * TM;
    if (m0 >= cnt) return;
    int n0 = blockIdx.x * TN;
    int tid = threadIdx.x;
    int lane = tid & 31;
    int wid = tid >> 5;
    int wm = wid >> 2, wn = wid & 3;
    uint32_t ab = smem_u32(smem) + SOFF;
    int* rowpr = (int*)smem;
    __shared__ int s_base;
    if (tid < TM) {
        int m = m0 + tid;
        rowpr[tid] = (m < cnt) ? g_list[e][m] : -1;
    }
    if (tid == 0) s_base = expert_off(e) + m0;
    __syncthreads();

    int base_m = s_base;
    int nvalid = cnt - m0; if (nvalid > TM) nvalid = TM;
    const __half* Bp = g_W2t + ((size_t)e*ND + (size_t)n0)*NH;
    const int T = NH / KC;  // 64

    float acc[4][8][4];
    #pragma unroll
    for (int a = 0; a < 4; a++)
        #pragma unroll
        for (int b = 0; b < 8; b++)
            #pragma unroll
            for (int c = 0; c < 4; c++) acc[a][b][c] = 0.f;

    for (int s = 0; s < NSTG-1; s++) g2_load(ab, s, base_m, nvalid, Bp, tid);

    for (int t = 0; t < T; t++) {
        if (t < T-1) CP_WAIT1(); else CP_WAIT0();
        __syncthreads();
        if (t + NSTG - 1 < T) g2_load(ab, t + NSTG - 1, base_m, nvalid, Bp, tid);
        chunk_mma(ab, t % NSTG, wm, wn, lane, acc);
    }

    const float* bb = b2 + (size_t)e*ND + n0;
    #pragma unroll
    for (int mt = 0; mt < 4; mt++) {
        int r0 = wm*64 + mt*16 + (lane >> 2);
        #pragma unroll
        for (int half = 0; half < 2; half++) {
            int r = r0 + half*8;
            int pr = rowpr[r];
            if (pr < 0) continue;
            float* yp = g_y + (size_t)pr*ND + n0;
            #pragma unroll
            for (int nt = 0; nt < 8; nt++) {
                int cc = wn*64 + nt*8 + 2*(lane & 3);
                float2 o;
                o.x = acc[mt][nt][half*2+0] + bb[cc];
                o.y = acc[mt][nt][half*2+1] + bb[cc+1];
                *(float2*)(yp + cc) = o;
            }
        }
    }
}

// ---------------- combine ----------------
__global__ __launch_bounds__(256) void combine_kernel(float* __restrict__ out) {
    size_t i4 = (size_t)blockIdx.x*256 + threadIdx.x;
    size_t base = i4 * 4;
    int t = (int)(base >> 10);
    int d = (int)(base & (ND-1));
    float g0 = g_gate[2*t], g1 = g_gate[2*t+1];
    float4 y0 = *(const float4*)(g_y + (size_t)(2*t)*ND + d);
    float4 y1 = *(const float4*)(g_y + (size_t)(2*t+1)*ND + d);
    float4 o;
    o.x = g0*y0.x + g1*y1.x;
    o.y = g0*y0.y + g1*y1.y;
    o.z = g0*y0.z + g1*y1.z;
    o.w = g0*y0.w + g1*y1.w;
    *(float4*)(out + base) = o;
}

// ---------------- finalize aux losses ----------------
__global__ void finalize_kernel(float* __restrict__ out) {
    const float invT = 1.f/(float)NTOK;
    float lb = 0.f;
    #pragma unroll
    for (int e = 0; e < NE; e++) {
        float im = g_imp[e]*invT - 1.f/NE;
        lb += im*im;
    }
    lb *= 1.f/NE;
    float rz  = g_rz  * invT;
    float ent = g_ent * invT;
    size_t o = (size_t)NTOK*ND;
    out[o+0] = lb;
    out[o+1] = rz;
    out[o+2] = ent;
    out[o+3] = lb + 0.001f*rz - 0.001f*ent;
}

// ---------------- launch ----------------
extern "C" void kernel_launch(void* const* d_in, const int* in_sizes, int n_in,
                              void* d_out, int out_size) {
    const float* x      = (const float*)d_in[0];
    const float* ctx    = (const float*)d_in[1];
    const float* qual   = (const float*)d_in[2];
    const float* rn_g   = (const float*)d_in[3];
    const float* rn_b   = (const float*)d_in[4];
    const float* cn_g   = (const float*)d_in[5];
    const float* cn_b   = (const float*)d_in[6];
    const float* ctx_W  = (const float*)d_in[7];
    const float* ctx_b  = (const float*)d_in[8];
    const float* q_W    = (const float*)d_in[9];
    const float* q_b    = (const float*)d_in[10];
    const float* r_W    = (const float*)d_in[11];
    const float* r_b    = (const float*)d_in[12];
    const float* temp   = (const float*)d_in[13];
    const float* W1     = (const float*)d_in[14];
    const float* b1     = (const float*)d_in[15];
    const float* W2     = (const float*)d_in[16];
    const float* b2     = (const float*)d_in[17];
    float* out = (float*)d_out;

    cudaFuncSetAttribute(gemm1_mma, cudaFuncAttributeMaxDynamicSharedMemorySize, DSMEM);
    cudaFuncSetAttribute(gemm2_mma, cudaFuncAttributeMaxDynamicSharedMemorySize, DSMEM);

    // our 4th launch is the one ncu profiles -> keep gemm1 there
    prep_all<<<ND+1, 256>>>(ctx_W, r_W, ctx_b, q_W, q_b, r_b);           // 1
    transpose_h<<<dim3(NH/32, ND/32, NE), dim3(32, 8)>>>(W1, ND, NH, 0); // 2
    router_kernel<<<NTOK/8, 256>>>(x, ctx, qual, rn_g, rn_b, cn_g, cn_b, r_W, temp); // 3
    gemm1_mma<<<dim3(NH/TN, NPAIR/TM, NE), NTHR, DSMEM>>>(b1);           // 4 <- profiled
    transpose_h<<<dim3(ND/32, NH/32, NE), dim3(32, 8)>>>(W2, NH, ND, 1); // 5
    gemm2_mma<<<dim3(ND/TN, NPAIR/TM, NE), NTHR, DSMEM>>>(b2);           // 6
    combine_kernel<<<(NTOK*ND)/(256*4), 256>>>(out);                     // 7
    finalize_kernel<<<1, 1>>>(out);                                      // 8
}

// round 11
// speedup vs baseline: 1.1047x; 1.1047x over previous
#include <cuda_runtime.h>
#include <cuda_fp16.h>
#include <math.h>
#include <stdint.h>

#define NB 4
#define NS 2048
#define ND 1024
#define NH 4096
#define NE 8
#define NTOK (NB*NS)      /* 8192 tokens */
#define NPAIR (NTOK*2)    /* 16384 (token,expert) pairs */

#define TM 128
#define TN 128
#define KC 64               /* K per stage (64 halfs = 128 B rows) */
#define NSTG 3
#define ROWB 144            /* padded row: 128 B data + 16 B pad */
#define ABYTES (128*ROWB)   /* 18432 B per matrix per stage */
#define STGB (2*ABYTES)
#define SOFF 512
#define DSMEM (SOFF + NSTG*STGB)   /* 111104 B -> 2 CTAs/SM */

// ---------------- device scratch (static allocations only) ----------------
__device__ float g_M[ND*NE];
__device__ float g_cvec[NE];
__device__ float g_qv[NE];
__device__ int   g_cnt[NE];
__device__ int   g_list[NE][NTOK];
__device__ float g_gate[NPAIR];
__device__ __half g_xh[(size_t)NTOK*ND];      // fp16 x (written by router)
__device__ __half g_W1t[(size_t)NE*NH*ND];    // W1^T  [e][n][k], fp16
__device__ __half g_W2t[(size_t)NE*ND*NH];    // W2^T  [e][n][k], fp16
__device__ __half g_h[(size_t)NPAIR*NH];      // hidden acts, fp16
__device__ float g_y[(size_t)NPAIR*ND];       // per-pair outputs, fp32
__device__ float g_imp[NE];
__device__ float g_rz;
__device__ float g_ent;

// ---------------- helpers ----------------
__device__ __forceinline__ uint32_t smem_u32(const void* p) {
    uint32_t a;
    asm("{ .reg .u64 t; cvta.to.shared.u64 t, %1; cvt.u32.u64 %0, t; }"
        : "=r"(a) : "l"(p));
    return a;
}
__device__ __forceinline__ void cp16(uint32_t dst, const void* src, uint32_t bytes) {
    asm volatile("cp.async.cg.shared.global [%0], [%1], 16, %2;\n"
                 :: "r"(dst), "l"(src), "r"(bytes) : "memory");
}
#define CP_COMMIT() asm volatile("cp.async.commit_group;\n" ::: "memory")
#define CP_WAIT2()  asm volatile("cp.async.wait_group 2;\n" ::: "memory")
#define CP_WAIT0()  asm volatile("cp.async.wait_group 0;\n" ::: "memory")

__device__ __forceinline__ void mma_f16(float* c, const uint32_t* a, const uint32_t* b) {
    asm volatile("mma.sync.aligned.m16n8k16.row.col.f32.f16.f16.f32 "
        "{%0,%1,%2,%3}, {%4,%5,%6,%7}, {%8,%9}, {%0,%1,%2,%3};"
        : "+f"(c[0]), "+f"(c[1]), "+f"(c[2]), "+f"(c[3])
        : "r"(a[0]), "r"(a[1]), "r"(a[2]), "r"(a[3]), "r"(b[0]), "r"(b[1]));
}
__device__ __forceinline__ void ldsm4(uint32_t* r, uint32_t a) {
    asm volatile("ldmatrix.sync.aligned.m8n8.x4.shared.b16 {%0,%1,%2,%3}, [%4];"
        : "=r"(r[0]), "=r"(r[1]), "=r"(r[2]), "=r"(r[3]) : "r"(a));
}

// ---------------- fused prep ----------------
__device__ __forceinline__ float blk_sum(float v, float* sred) {
    int tid = threadIdx.x;
    sred[tid] = v;
    __syncthreads();
    #pragma unroll
    for (int o = 128; o > 0; o >>= 1) {
        if (tid < o) sred[tid] += sred[tid + o];
        __syncthreads();
    }
    float r = sred[0];
    __syncthreads();
    return r;
}

__global__ __launch_bounds__(256) void prep_all(
        const float* __restrict__ ctx_W, const float* __restrict__ r_W,
        const float* __restrict__ ctx_b, const float* __restrict__ q_W,
        const float* __restrict__ q_b,  const float* __restrict__ r_b) {
    __shared__ float sred[256];
    int tid = threadIdx.x;
    if (blockIdx.x == 0) {
        if (tid < NE) { g_cnt[tid] = 0; g_imp[tid] = 0.f; }
        if (tid == 0) { g_rz = 0.f; g_ent = 0.f; }
        float pc[NE], pq[NE];
        #pragma unroll
        for (int e = 0; e < NE; e++) { pc[e] = 0.f; pq[e] = 0.f; }
        for (int d = tid; d < ND; d += 256) {
            float cb = ctx_b[d] + q_b[d];
            float qw = q_W[d];
            #pragma unroll
            for (int e = 0; e < NE; e++) {
                pc[e] += cb * r_W[d*NE + e];
                pq[e] += qw * r_W[d*NE + e];
            }
        }
        #pragma unroll
        for (int e = 0; e < NE; e++) {
            float vc = blk_sum(pc[e], sred);
            float vq = blk_sum(pq[e], sred);
            if (tid == 0) { g_cvec[e] = vc + r_b[e]; g_qv[e] = vq; }
        }
    } else {
        int j = blockIdx.x - 1;
        float part[NE];
        #pragma unroll
        for (int e = 0; e < NE; e++) part[e] = 0.f;
        for (int d = tid; d < ND; d += 256) {
            float w = ctx_W[(size_t)j*ND + d];
            #pragma unroll
            for (int e = 0; e < NE; e++) part[e] += w * r_W[d*NE + e];
        }
        #pragma unroll
        for (int e = 0; e < NE; e++) {
            float v = blk_sum(part[e], sred);
            if (tid == 0) g_M[j*NE + e] = v;
        }
    }
}

// ---------------- fused transpose of BOTH weights + fp16 ----------------
// z in [0,16): z<8 -> W1 expert z (R=ND, C=NH); else W2 expert z-8 (R=NH, C=ND).
__global__ void transpose_both(const float* __restrict__ W1,
                               const float* __restrict__ W2) {
    __shared__ float t[32][33];
    int z = blockIdx.z;
    const float* S;
    __half* D;
    int R, C;
    if (z < NE) { S = W1 + (size_t)z*ND*NH; D = g_W1t + (size_t)z*ND*NH; R = ND; C = NH; }
    else        { S = W2 + (size_t)(z-NE)*NH*ND; D = g_W2t + (size_t)(z-NE)*NH*ND; R = NH; C = ND; }
    int c0 = blockIdx.x*32, r0 = blockIdx.y*32;
    if (c0 >= C || r0 >= R) return;
    int tx = threadIdx.x, ty = threadIdx.y;
    #pragma unroll
    for (int i = 0; i < 32; i += 8)
        t[ty+i][tx] = S[(size_t)(r0+ty+i)*C + c0+tx];
    __syncthreads();
    #pragma unroll
    for (int i = 0; i < 32; i += 8)
        D[(size_t)(c0+ty+i)*R + r0+tx] = __float2half(t[tx][ty+i]);
}

// ---------------- router: one warp per token ----------------
__global__ __launch_bounds__(256) void router_kernel(
        const float* __restrict__ x, const float* __restrict__ ctx,
        const float* __restrict__ quality,
        const float* __restrict__ rn_g, const float* __restrict__ rn_b,
        const float* __restrict__ cn_g, const float* __restrict__ cn_b,
        const float* __restrict__ r_W, const float* __restrict__ temp_p) {
    int wid = threadIdx.x >> 5, lane = threadIdx.x & 31;
    int t = blockIdx.x*8 + wid;

    const float4* xr = (const float4*)(x   + (size_t)t*ND);
    const float4* cr = (const float4*)(ctx + (size_t)t*ND);
    float4 xv[8], cv[8];
    #pragma unroll
    for (int i = 0; i < 8; i++) { xv[i] = xr[lane + 32*i]; cv[i] = cr[lane + 32*i]; }

    #pragma unroll
    for (int i = 0; i < 8; i++) {
        __half2 h0 = __floats2half2_rn(xv[i].x, xv[i].y);
        __half2 h1 = __floats2half2_rn(xv[i].z, xv[i].w);
        uint2 o = make_uint2(*(uint32_t*)&h0, *(uint32_t*)&h1);
        *(uint2*)(g_xh + (size_t)t*ND + (lane + 32*i)*4) = o;
    }

    float sx=0.f, sxx=0.f, sc=0.f, scc=0.f;
    #pragma unroll
    for (int i = 0; i < 8; i++) {
        sx  += xv[i].x + xv[i].y + xv[i].z + xv[i].w;
        sxx += xv[i].x*xv[i].x + xv[i].y*xv[i].y + xv[i].z*xv[i].z + xv[i].w*xv[i].w;
        sc  += cv[i].x + cv[i].y + cv[i].z + cv[i].w;
        scc += cv[i].x*cv[i].x + cv[i].y*cv[i].y + cv[i].z*cv[i].z + cv[i].w*cv[i].w;
    }
    #pragma unroll
    for (int o = 16; o; o >>= 1) {
        sx  += __shfl_xor_sync(0xFFFFFFFFu, sx,  o);
        sxx += __shfl_xor_sync(0xFFFFFFFFu, sxx, o);
        sc  += __shfl_xor_sync(0xFFFFFFFFu, sc,  o);
        scc += __shfl_xor_sync(0xFFFFFFFFu, scc, o);
    }
    float mu_x = sx*(1.f/ND), mu_c = sc*(1.f/ND);
    float rs_x = rsqrtf(sxx*(1.f/ND) - mu_x*mu_x + 1e-5f);
    float rs_c = rsqrtf(scc*(1.f/ND) - mu_c*mu_c + 1e-5f);

    float part[NE];
    #pragma unroll
    for (int e = 0; e < NE; e++) part[e] = 0.f;
    #pragma unroll
    for (int i = 0; i < 8; i++) {
        float xa[4] = {xv[i].x, xv[i].y, xv[i].z, xv[i].w};
        float ca[4] = {cv[i].x, cv[i].y, cv[i].z, cv[i].w};
        #pragma unroll
        for (int j = 0; j < 4; j++) {
            int d = (lane + 32*i)*4 + j;
            float nx = (xa[j]-mu_x)*rs_x*rn_g[d] + rn_b[d];
            float nc = (ca[j]-mu_c)*rs_c*cn_g[d] + cn_b[d];
            const float* rw = r_W + d*NE;
            const float* mm = g_M + d*NE;
            #pragma unroll
            for (int e = 0; e < NE; e++) part[e] += nx*rw[e] + nc*mm[e];
        }
    }
    #pragma unroll
    for (int e = 0; e < NE; e++)
        #pragma unroll
        for (int o = 16; o; o >>= 1)
            part[e] += __shfl_xor_sync(0xFFFFFFFFu, part[e], o);

    __shared__ float simp[8][NE];
    __shared__ float srz[8];
    __shared__ float sent[8];

    if (lane == 0) {
        float temp = fmaxf(temp_p[0], 0.25f);
        float q = quality[t / NS];
        float lg[NE];
        #pragma unroll
        for (int e = 0; e < NE; e++)
            lg[e] = (part[e] + g_cvec[e] + q*g_qv[e]) / temp;

        int i1 = 0;
        #pragma unroll
        for (int e = 1; e < NE; e++) if (lg[e] > lg[i1]) i1 = e;
        int i2 = (i1 == 0) ? 1 : 0;
        #pragma unroll
        for (int e = 0; e < NE; e++) {
            if (e == i1 || e == i2) continue;
            if (lg[e] > lg[i2]) i2 = e;
        }

        float mx = lg[0];
        #pragma unroll
        for (int e = 1; e < NE; e++) mx = fmaxf(mx, lg[e]);
        float se = 0.f;
        #pragma unroll
        for (int e = 0; e < NE; e++) se += expf(lg[e]-mx);
        float lse = mx + logf(se);
        float inv_se = 1.f/se;
        float ent = 0.f;
        #pragma unroll
        for (int e = 0; e < NE; e++) {
            float p = expf(lg[e]-mx)*inv_se;
            simp[wid][e] = p;
            ent -= p * (lg[e]-lse);
        }
        srz[wid]  = lse*lse;
        sent[wid] = ent;

        float ex = expf(lg[i2]-lg[i1]);
        float inv = 1.f/(1.f+ex);
        g_gate[2*t]   = inv;
        g_gate[2*t+1] = ex*inv;
        int p1 = atomicAdd(&g_cnt[i1], 1);
        g_list[i1][p1] = 2*t;
        int p2 = atomicAdd(&g_cnt[i2], 1);
        g_list[i2][p2] = 2*t+1;
    }
    __syncthreads();
    int tid = threadIdx.x;
    if (tid < NE) {
        float s = 0.f;
        #pragma unroll
        for (int w = 0; w < 8; w++) s += simp[w][tid];
        atomicAdd(&g_imp[tid], s);
    } else if (tid == 8) {
        float s = 0.f;
        #pragma unroll
        for (int w = 0; w < 8; w++) s += srz[w];
        atomicAdd(&g_rz, s);
    } else if (tid == 9) {
        float s = 0.f;
        #pragma unroll
        for (int w = 0; w < 8; w++) s += sent[w];
        atomicAdd(&g_ent, s);
    }
}

// ---------------- stage loaders (fp16 rows: 128 B data + 16 B pad) ----------------
__device__ __forceinline__ void g1_load(uint32_t ab, int s,
        const __half* __restrict__ Bp, const int* rowpr, int tid) {
    int buf = s % NSTG;
    int k0 = s * KC;
    uint32_t abase = ab + buf*STGB;
    uint32_t bbase = abase + ABYTES;
    #pragma unroll
    for (int i = 0; i < 4; i++) {
        int u = tid + 256*i; int r = u >> 3, sj = u & 7;
        int pr = rowpr[r];
        const __half* src = (pr >= 0) ? (g_xh + ((size_t)(pr >> 1))*ND + k0 + sj*8) : g_xh;
        cp16(abase + r*ROWB + sj*16, src, (pr >= 0) ? 16u : 0u);
    }
    #pragma unroll
    for (int i = 0; i < 4; i++) {
        int u = tid + 256*i; int r = u >> 3, sj = u & 7;
        cp16(bbase + r*ROWB + sj*16, Bp + (size_t)r*ND + k0 + sj*8, 16u);
    }
    CP_COMMIT();
}

__device__ __forceinline__ void g2_load(uint32_t ab, int s,
        int base_m, int nvalid, const __half* __restrict__ Bp, int tid) {
    int buf = s % NSTG;
    int k0 = s * KC;
    uint32_t abase = ab + buf*STGB;
    uint32_t bbase = abase + ABYTES;
    #pragma unroll
    for (int i = 0; i < 4; i++) {
        int u = tid + 256*i; int r = u >> 3, sj = u & 7;
        bool ok = (r < nvalid);
        const __half* src = g_h + (size_t)(base_m + (ok ? r : 0))*NH + k0 + sj*8;
        cp16(abase + r*ROWB + sj*16, src, ok ? 16u : 0u);
    }
    #pragma unroll
    for (int i = 0; i < 4; i++) {
        int u = tid + 256*i; int r = u >> 3, sj = u & 7;
        cp16(bbase + r*ROWB + sj*16, Bp + (size_t)r*NH + k0 + sj*8, 16u);
    }
    CP_COMMIT();
}

// ---------------- chunk compute: 8 warps x (64x32), fp16 K=64, ldmatrix ----------------
__device__ __forceinline__ void chunk_mma(uint32_t ab, int buf,
        int wm, int wn, int lane, float acc[4][4][4]) {
    uint32_t As = ab + buf*STGB;
    uint32_t Bs = As + ABYTES;
    int l7 = lane & 7;
    int arow = wm*64 + ((lane>>3)&1)*8 + l7;
    uint32_t acol = (uint32_t)((lane>>4)*16);
    int brow = wn*32 + ((lane>>4)&1)*8 + l7;
    uint32_t bcol = (uint32_t)(((lane>>3)&1)*16);
    #pragma unroll
    for (int ks = 0; ks < 4; ks++) {
        uint32_t kb = ks*32;
        uint32_t af[4][4], bregs[2][4];
        #pragma unroll
        for (int mt = 0; mt < 4; mt++)
            ldsm4(af[mt], As + (uint32_t)(arow + mt*16)*ROWB + kb + acol);
        #pragma unroll
        for (int p = 0; p < 2; p++)
            ldsm4(bregs[p], Bs + (uint32_t)(brow + p*16)*ROWB + kb + bcol);
        #pragma unroll
        for (int mt = 0; mt < 4; mt++)
            #pragma unroll
            for (int nt = 0; nt < 4; nt++)
                mma_f16(acc[mt][nt], af[mt], &bregs[nt>>1][(nt&1)*2]);
    }
}

// ---------------- expert offset ----------------
__device__ __forceinline__ int expert_off(int e) {
    int s = 0;
    #pragma unroll
    for (int k = 0; k < NE; k++) if (k < e) s += g_cnt[k];
    return s;
}

// ---------------- GEMM1: h = h16(gelu(x @ W1 + b1)) ----------------
__global__ __launch_bounds__(256) void gemm1_mma(const float* __restrict__ b1) {
    extern __shared__ char smem[];
    int e = blockIdx.z;
    int cnt = g_cnt[e];
    int m0 = blockIdx.y * TM;
    if (m0 >= cnt) return;
    int n0 = blockIdx.x * TN;
    int tid = threadIdx.x;
    int lane = tid & 31;
    int wm = (tid >> 5) & 1, wn = tid >> 6;
    uint32_t ab = smem_u32(smem) + SOFF;
    int* rowpr = (int*)smem;
    __shared__ int s_base;
    if (tid < TM) {
        int m = m0 + tid;
        rowpr[tid] = (m < cnt) ? g_list[e][m] : -1;
    }
    if (tid == 0) s_base = expert_off(e) + m0;
    __syncthreads();

    const __half* Bp = g_W1t + ((size_t)e*NH + (size_t)n0)*ND;
    const int T = ND / KC;  // 16

    float acc[4][4][4];
    #pragma unroll
    for (int a = 0; a < 4; a++)
        #pragma unroll
        for (int b = 0; b < 4; b++)
            #pragma unroll
            for (int c = 0; c < 4; c++) acc[a][b][c] = 0.f;

    for (int s = 0; s < NSTG; s++) g1_load(ab, s, Bp, rowpr, tid);

    for (int t = 0; t < T; t++) {
        int buf = t % NSTG;
        if (t + NSTG <= T) CP_WAIT2(); else CP_WAIT0();
        __syncthreads();
        chunk_mma(ab, buf, wm, wn, lane, acc);
        __syncthreads();
        if (t + NSTG < T) g1_load(ab, t + NSTG, Bp, rowpr, tid);
    }

    int base_m = s_base;
    const float* bb = b1 + (size_t)e*NH + n0;
    #pragma unroll
    for (int mt = 0; mt < 4; mt++) {
        int r0 = wm*64 + mt*16 + (lane >> 2);
        #pragma unroll
        for (int half = 0; half < 2; half++) {
            int r = r0 + half*8;
            int pr = rowpr[r];
            if (pr < 0) continue;
            __half* hp = g_h + (size_t)(base_m + r)*NH + n0;
            #pragma unroll
            for (int nt = 0; nt < 4; nt++) {
                int cc = wn*32 + nt*8 + 2*(lane & 3);
                float v0 = acc[mt][nt][half*2+0] + bb[cc];
                float v1 = acc[mt][nt][half*2+1] + bb[cc+1];
                __half2 o = __floats2half2_rn(v0 * normcdff(v0), v1 * normcdff(v1));
                *(__half2*)(hp + cc) = o;
            }
        }
    }
}

// ---------------- GEMM2: y = h @ W2 + b2 ----------------
__global__ __launch_bounds__(256) void gemm2_mma(const float* __restrict__ b2) {
    extern __shared__ char smem[];
    int e = blockIdx.z;
    int cnt = g_cnt[e];
    int m0 = blockIdx.y * TM;
    if (m0 >= cnt) return;
    int n0 = blockIdx.x * TN;
    int tid = threadIdx.x;
    int lane = tid & 31;
    int wm = (tid >> 5) & 1, wn = tid >> 6;
    uint32_t ab = smem_u32(smem) + SOFF;
    int* rowpr = (int*)smem;
    __shared__ int s_base;
    if (tid < TM) {
        int m = m0 + tid;
        rowpr[tid] = (m < cnt) ? g_list[e][m] : -1;
    }
    if (tid == 0) s_base = expert_off(e) + m0;
    __syncthreads();

    int base_m = s_base;
    int nvalid = cnt - m0; if (nvalid > TM) nvalid = TM;
    const __half* Bp = g_W2t + ((size_t)e*ND + (size_t)n0)*NH;
    const int T = NH / KC;  // 64

    float acc[4][4][4];
    #pragma unroll
    for (int a = 0; a < 4; a++)
        #pragma unroll
        for (int b = 0; b < 4; b++)
            #pragma unroll
            for (int c = 0; c < 4; c++) acc[a][b][c] = 0.f;

    for (int s = 0; s < NSTG; s++) g2_load(ab, s, base_m, nvalid, Bp, tid);

    for (int t = 0; t < T; t++) {
        int buf = t % NSTG;
        if (t + NSTG <= T) CP_WAIT2(); else CP_WAIT0();
        __syncthreads();
        chunk_mma(ab, buf, wm, wn, lane, acc);
        __syncthreads();
        if (t + NSTG < T) g2_load(ab, t + NSTG, base_m, nvalid, Bp, tid);
    }

    const float* bb = b2 + (size_t)e*ND + n0;
    #pragma unroll
    for (int mt = 0; mt < 4; mt++) {
        int r0 = wm*64 + mt*16 + (lane >> 2);
        #pragma unroll
        for (int half = 0; half < 2; half++) {
            int r = r0 + half*8;
            int pr = rowpr[r];
            if (pr < 0) continue;
            float* yp = g_y + (size_t)pr*ND + n0;
            #pragma unroll
            for (int nt = 0; nt < 4; nt++) {
                int cc = wn*32 + nt*8 + 2*(lane & 3);
                float2 o;
                o.x = acc[mt][nt][half*2+0] + bb[cc];
                o.y = acc[mt][nt][half*2+1] + bb[cc+1];
                *(float2*)(yp + cc) = o;
            }
        }
    }
}

// ---------------- combine ----------------
__global__ __launch_bounds__(256) void combine_kernel(float* __restrict__ out) {
    size_t i4 = (size_t)blockIdx.x*256 + threadIdx.x;
    size_t base = i4 * 4;
    int t = (int)(base >> 10);
    int d = (int)(base & (ND-1));
    float g0 = g_gate[2*t], g1 = g_gate[2*t+1];
    float4 y0 = *(const float4*)(g_y + (size_t)(2*t)*ND + d);
    float4 y1 = *(const float4*)(g_y + (size_t)(2*t+1)*ND + d);
    float4 o;
    o.x = g0*y0.x + g1*y1.x;
    o.y = g0*y0.y + g1*y1.y;
    o.z = g0*y0.z + g1*y1.z;
    o.w = g0*y0.w + g1*y1.w;
    *(float4*)(out + base) = o;
}

// ---------------- finalize aux losses ----------------
__global__ void finalize_kernel(float* __restrict__ out) {
    const float invT = 1.f/(float)NTOK;
    float lb = 0.f;
    #pragma unroll
    for (int e = 0; e < NE; e++) {
        float im = g_imp[e]*invT - 1.f/NE;
        lb += im*im;
    }
    lb *= 1.f/NE;
    float rz  = g_rz  * invT;
    float ent = g_ent * invT;
    size_t o = (size_t)NTOK*ND;
    out[o+0] = lb;
    out[o+1] = rz;
    out[o+2] = ent;
    out[o+3] = lb + 0.001f*rz - 0.001f*ent;
}

// ---------------- launch ----------------
extern "C" void kernel_launch(void* const* d_in, const int* in_sizes, int n_in,
                              void* d_out, int out_size) {
    const float* x      = (const float*)d_in[0];
    const float* ctx    = (const float*)d_in[1];
    const float* qual   = (const float*)d_in[2];
    const float* rn_g   = (const float*)d_in[3];
    const float* rn_b   = (const float*)d_in[4];
    const float* cn_g   = (const float*)d_in[5];
    const float* cn_b   = (const float*)d_in[6];
    const float* ctx_W  = (const float*)d_in[7];
    const float* ctx_b  = (const float*)d_in[8];
    const float* q_W    = (const float*)d_in[9];
    const float* q_b    = (const float*)d_in[10];
    const float* r_W    = (const float*)d_in[11];
    const float* r_b    = (const float*)d_in[12];
    const float* temp   = (const float*)d_in[13];
    const float* W1     = (const float*)d_in[14];
    const float* b1     = (const float*)d_in[15];
    const float* W2     = (const float*)d_in[16];
    const float* b2     = (const float*)d_in[17];
    float* out = (float*)d_out;

    cudaFuncSetAttribute(gemm1_mma, cudaFuncAttributeMaxDynamicSharedMemorySize, DSMEM);
    cudaFuncSetAttribute(gemm2_mma, cudaFuncAttributeMaxDynamicSharedMemorySize, DSMEM);

    // our 4th launch is the one ncu profiles -> keep gemm1 there
    prep_all<<<ND+1, 256>>>(ctx_W, r_W, ctx_b, q_W, q_b, r_b);           // 1
    transpose_both<<<dim3(NH/32, NH/32, 2*NE), dim3(32, 8)>>>(W1, W2);   // 2 (grid covers max dims; OOB blocks exit)
    router_kernel<<<NTOK/8, 256>>>(x, ctx, qual, rn_g, rn_b, cn_g, cn_b, r_W, temp); // 3
    gemm1_mma<<<dim3(NH/TN, NPAIR/TM, NE), 256, DSMEM>>>(b1);            // 4 <- profiled
    gemm2_mma<<<dim3(ND/TN, NPAIR/TM, NE), 256, DSMEM>>>(b2);            // 5
    combine_kernel<<<(NTOK*ND)/(256*4), 256>>>(out);                     // 6
    finalize_kernel<<<1, 1>>>(out);                                      // 7
}

// round 12
// speedup vs baseline: 1.1798x; 1.0680x over previous
#include <cuda_runtime.h>
#include <cuda_fp16.h>
#include <math.h>
#include <stdint.h>

#define NB 4
#define NS 2048
#define ND 1024
#define NH 4096
#define NE 8
#define NTOK (NB*NS)      /* 8192 tokens */
#define NPAIR (NTOK*2)    /* 16384 (token,expert) pairs */

#define TM 128
#define TN 128
#define KC 64               /* K per stage (64 halfs = 128 B rows) */
#define NSTG 3
#define ROWB 144            /* padded row: 128 B data + 16 B pad */
#define ABYTES (128*ROWB)   /* 18432 B per matrix per stage */
#define STGB (2*ABYTES)
#define SOFF 512
#define DSMEM (SOFF + NSTG*STGB)   /* 111104 B -> 2 CTAs/SM */

// ---------------- device scratch (static allocations only) ----------------
__device__ float g_M[ND*NE];
__device__ float g_cvec[NE];
__device__ float g_qv[NE];
__device__ int   g_cnt[NE];
__device__ int   g_list[NE][NTOK];
__device__ float g_gate[NPAIR];
__device__ __half g_xh[(size_t)NTOK*ND];      // fp16 x (written by router)
__device__ __half g_W1t[(size_t)NE*NH*ND];    // W1^T  [e][n][k], fp16
__device__ __half g_W2t[(size_t)NE*ND*NH];    // W2^T  [e][n][k], fp16
__device__ __half g_h[(size_t)NPAIR*NH];      // hidden acts, fp16
__device__ float g_y[(size_t)NPAIR*ND];       // per-pair outputs, fp32
__device__ float g_imp[NE];
__device__ float g_rz;
__device__ float g_ent;

// ---------------- helpers ----------------
__device__ __forceinline__ uint32_t smem_u32(const void* p) {
    uint32_t a;
    asm("{ .reg .u64 t; cvta.to.shared.u64 t, %1; cvt.u32.u64 %0, t; }"
        : "=r"(a) : "l"(p));
    return a;
}
__device__ __forceinline__ void cp16(uint32_t dst, const void* src, uint32_t bytes) {
    asm volatile("cp.async.cg.shared.global [%0], [%1], 16, %2;\n"
                 :: "r"(dst), "l"(src), "r"(bytes) : "memory");
}
#define CP_COMMIT() asm volatile("cp.async.commit_group;\n" ::: "memory")
#define CP_WAIT2()  asm volatile("cp.async.wait_group 2;\n" ::: "memory")
#define CP_WAIT0()  asm volatile("cp.async.wait_group 0;\n" ::: "memory")

__device__ __forceinline__ void mma_f16(float* c, const uint32_t* a, const uint32_t* b) {
    asm volatile("mma.sync.aligned.m16n8k16.row.col.f32.f16.f16.f32 "
        "{%0,%1,%2,%3}, {%4,%5,%6,%7}, {%8,%9}, {%0,%1,%2,%3};"
        : "+f"(c[0]), "+f"(c[1]), "+f"(c[2]), "+f"(c[3])
        : "r"(a[0]), "r"(a[1]), "r"(a[2]), "r"(a[3]), "r"(b[0]), "r"(b[1]));
}
__device__ __forceinline__ void ldsm4(uint32_t* r, uint32_t a) {
    asm volatile("ldmatrix.sync.aligned.m8n8.x4.shared.b16 {%0,%1,%2,%3}, [%4];"
        : "=r"(r[0]), "=r"(r[1]), "=r"(r[2]), "=r"(r[3]) : "r"(a));
}

// ---------------- fused prep ----------------
__device__ __forceinline__ float blk_sum(float v, float* sred) {
    int tid = threadIdx.x;
    sred[tid] = v;
    __syncthreads();
    #pragma unroll
    for (int o = 128; o > 0; o >>= 1) {
        if (tid < o) sred[tid] += sred[tid + o];
        __syncthreads();
    }
    float r = sred[0];
    __syncthreads();
    return r;
}

__global__ __launch_bounds__(256) void prep_all(
        const float* __restrict__ ctx_W, const float* __restrict__ r_W,
        const float* __restrict__ ctx_b, const float* __restrict__ q_W,
        const float* __restrict__ q_b,  const float* __restrict__ r_b) {
    __shared__ float sred[256];
    int tid = threadIdx.x;
    if (blockIdx.x == 0) {
        if (tid < NE) { g_cnt[tid] = 0; g_imp[tid] = 0.f; }
        if (tid == 0) { g_rz = 0.f; g_ent = 0.f; }
        float pc[NE], pq[NE];
        #pragma unroll
        for (int e = 0; e < NE; e++) { pc[e] = 0.f; pq[e] = 0.f; }
        for (int d = tid; d < ND; d += 256) {
            float cb = ctx_b[d] + q_b[d];
            float qw = q_W[d];
            #pragma unroll
            for (int e = 0; e < NE; e++) {
                pc[e] += cb * r_W[d*NE + e];
                pq[e] += qw * r_W[d*NE + e];
            }
        }
        #pragma unroll
        for (int e = 0; e < NE; e++) {
            float vc = blk_sum(pc[e], sred);
            float vq = blk_sum(pq[e], sred);
            if (tid == 0) { g_cvec[e] = vc + r_b[e]; g_qv[e] = vq; }
        }
    } else {
        int j = blockIdx.x - 1;
        float part[NE];
        #pragma unroll
        for (int e = 0; e < NE; e++) part[e] = 0.f;
        for (int d = tid; d < ND; d += 256) {
            float w = ctx_W[(size_t)j*ND + d];
            #pragma unroll
            for (int e = 0; e < NE; e++) part[e] += w * r_W[d*NE + e];
        }
        #pragma unroll
        for (int e = 0; e < NE; e++) {
            float v = blk_sum(part[e], sred);
            if (tid == 0) g_M[j*NE + e] = v;
        }
    }
}

// ---------------- transpose + fp16: D[e][c][r] = h(S[e][r][c]) ----------------
__global__ void transpose_h(const float* __restrict__ S, int R, int C, int which) {
    __shared__ float t[32][33];
    __half* D = which ? g_W2t : g_W1t;
    int e = blockIdx.z;
    S += (size_t)e*R*C; D += (size_t)e*R*C;
    int c0 = blockIdx.x*32, r0 = blockIdx.y*32;
    int tx = threadIdx.x, ty = threadIdx.y;
    #pragma unroll
    for (int i = 0; i < 32; i += 8)
        t[ty+i][tx] = S[(size_t)(r0+ty+i)*C + c0+tx];
    __syncthreads();
    #pragma unroll
    for (int i = 0; i < 32; i += 8)
        D[(size_t)(c0+ty+i)*R + r0+tx] = __float2half(t[tx][ty+i]);
}

// ---------------- router: one warp per token ----------------
__global__ __launch_bounds__(256) void router_kernel(
        const float* __restrict__ x, const float* __restrict__ ctx,
        const float* __restrict__ quality,
        const float* __restrict__ rn_g, const float* __restrict__ rn_b,
        const float* __restrict__ cn_g, const float* __restrict__ cn_b,
        const float* __restrict__ r_W, const float* __restrict__ temp_p) {
    int wid = threadIdx.x >> 5, lane = threadIdx.x & 31;
    int t = blockIdx.x*8 + wid;

    const float4* xr = (const float4*)(x   + (size_t)t*ND);
    const float4* cr = (const float4*)(ctx + (size_t)t*ND);
    float4 xv[8], cv[8];
    #pragma unroll
    for (int i = 0; i < 8; i++) { xv[i] = xr[lane + 32*i]; cv[i] = cr[lane + 32*i]; }

    #pragma unroll
    for (int i = 0; i < 8; i++) {
        __half2 h0 = __floats2half2_rn(xv[i].x, xv[i].y);
        __half2 h1 = __floats2half2_rn(xv[i].z, xv[i].w);
        uint2 o = make_uint2(*(uint32_t*)&h0, *(uint32_t*)&h1);
        *(uint2*)(g_xh + (size_t)t*ND + (lane + 32*i)*4) = o;
    }

    float sx=0.f, sxx=0.f, sc=0.f, scc=0.f;
    #pragma unroll
    for (int i = 0; i < 8; i++) {
        sx  += xv[i].x + xv[i].y + xv[i].z + xv[i].w;
        sxx += xv[i].x*xv[i].x + xv[i].y*xv[i].y + xv[i].z*xv[i].z + xv[i].w*xv[i].w;
        sc  += cv[i].x + cv[i].y + cv[i].z + cv[i].w;
        scc += cv[i].x*cv[i].x + cv[i].y*cv[i].y + cv[i].z*cv[i].z + cv[i].w*cv[i].w;
    }
    #pragma unroll
    for (int o = 16; o; o >>= 1) {
        sx  += __shfl_xor_sync(0xFFFFFFFFu, sx,  o);
        sxx += __shfl_xor_sync(0xFFFFFFFFu, sxx, o);
        sc  += __shfl_xor_sync(0xFFFFFFFFu, sc,  o);
        scc += __shfl_xor_sync(0xFFFFFFFFu, scc, o);
    }
    float mu_x = sx*(1.f/ND), mu_c = sc*(1.f/ND);
    float rs_x = rsqrtf(sxx*(1.f/ND) - mu_x*mu_x + 1e-5f);
    float rs_c = rsqrtf(scc*(1.f/ND) - mu_c*mu_c + 1e-5f);

    float part[NE];
    #pragma unroll
    for (int e = 0; e < NE; e++) part[e] = 0.f;
    #pragma unroll
    for (int i = 0; i < 8; i++) {
        float xa[4] = {xv[i].x, xv[i].y, xv[i].z, xv[i].w};
        float ca[4] = {cv[i].x, cv[i].y, cv[i].z, cv[i].w};
        #pragma unroll
        for (int j = 0; j < 4; j++) {
            int d = (lane + 32*i)*4 + j;
            float nx = (xa[j]-mu_x)*rs_x*rn_g[d] + rn_b[d];
            float nc = (ca[j]-mu_c)*rs_c*cn_g[d] + cn_b[d];
            const float* rw = r_W + d*NE;
            const float* mm = g_M + d*NE;
            #pragma unroll
            for (int e = 0; e < NE; e++) part[e] += nx*rw[e] + nc*mm[e];
        }
    }
    #pragma unroll
    for (int e = 0; e < NE; e++)
        #pragma unroll
        for (int o = 16; o; o >>= 1)
            part[e] += __shfl_xor_sync(0xFFFFFFFFu, part[e], o);

    __shared__ float simp[8][NE];
    __shared__ float srz[8];
    __shared__ float sent[8];

    if (lane == 0) {
        float temp = fmaxf(temp_p[0], 0.25f);
        float q = quality[t / NS];
        float lg[NE];
        #pragma unroll
        for (int e = 0; e < NE; e++)
            lg[e] = (part[e] + g_cvec[e] + q*g_qv[e]) / temp;

        int i1 = 0;
        #pragma unroll
        for (int e = 1; e < NE; e++) if (lg[e] > lg[i1]) i1 = e;
        int i2 = (i1 == 0) ? 1 : 0;
        #pragma unroll
        for (int e = 0; e < NE; e++) {
            if (e == i1 || e == i2) continue;
            if (lg[e] > lg[i2]) i2 = e;
        }

        float mx = lg[0];
        #pragma unroll
        for (int e = 1; e < NE; e++) mx = fmaxf(mx, lg[e]);
        float se = 0.f;
        #pragma unroll
        for (int e = 0; e < NE; e++) se += expf(lg[e]-mx);
        float lse = mx + logf(se);
        float inv_se = 1.f/se;
        float ent = 0.f;
        #pragma unroll
        for (int e = 0; e < NE; e++) {
            float p = expf(lg[e]-mx)*inv_se;
            simp[wid][e] = p;
            ent -= p * (lg[e]-lse);
        }
        srz[wid]  = lse*lse;
        sent[wid] = ent;

        float ex = expf(lg[i2]-lg[i1]);
        float inv = 1.f/(1.f+ex);
        g_gate[2*t]   = inv;
        g_gate[2*t+1] = ex*inv;
        int p1 = atomicAdd(&g_cnt[i1], 1);
        g_list[i1][p1] = 2*t;
        int p2 = atomicAdd(&g_cnt[i2], 1);
        g_list[i2][p2] = 2*t+1;
    }
    __syncthreads();
    int tid = threadIdx.x;
    if (tid < NE) {
        float s = 0.f;
        #pragma unroll
        for (int w = 0; w < 8; w++) s += simp[w][tid];
        atomicAdd(&g_imp[tid], s);
    } else if (tid == 8) {
        float s = 0.f;
        #pragma unroll
        for (int w = 0; w < 8; w++) s += srz[w];
        atomicAdd(&g_rz, s);
    } else if (tid == 9) {
        float s = 0.f;
        #pragma unroll
        for (int w = 0; w < 8; w++) s += sent[w];
        atomicAdd(&g_ent, s);
    }
}

// ---------------- stage loaders (fp16 rows: 128 B data + 16 B pad) ----------------
__device__ __forceinline__ void g1_load(uint32_t ab, int s,
        const __half* __restrict__ Bp, const int* rowpr, int tid) {
    int buf = s % NSTG;
    int k0 = s * KC;
    uint32_t abase = ab + buf*STGB;
    uint32_t bbase = abase + ABYTES;
    #pragma unroll
    for (int i = 0; i < 4; i++) {
        int u = tid + 256*i; int r = u >> 3, sj = u & 7;
        int pr = rowpr[r];
        const __half* src = (pr >= 0) ? (g_xh + ((size_t)(pr >> 1))*ND + k0 + sj*8) : g_xh;
        cp16(abase + r*ROWB + sj*16, src, (pr >= 0) ? 16u : 0u);
    }
    #pragma unroll
    for (int i = 0; i < 4; i++) {
        int u = tid + 256*i; int r = u >> 3, sj = u & 7;
        cp16(bbase + r*ROWB + sj*16, Bp + (size_t)r*ND + k0 + sj*8, 16u);
    }
    CP_COMMIT();
}

__device__ __forceinline__ void g2_load(uint32_t ab, int s,
        int base_m, int nvalid, const __half* __restrict__ Bp, int tid) {
    int buf = s % NSTG;
    int k0 = s * KC;
    uint32_t abase = ab + buf*STGB;
    uint32_t bbase = abase + ABYTES;
    #pragma unroll
    for (int i = 0; i < 4; i++) {
        int u = tid + 256*i; int r = u >> 3, sj = u & 7;
        bool ok = (r < nvalid);
        const __half* src = g_h + (size_t)(base_m + (ok ? r : 0))*NH + k0 + sj*8;
        cp16(abase + r*ROWB + sj*16, src, ok ? 16u : 0u);
    }
    #pragma unroll
    for (int i = 0; i < 4; i++) {
        int u = tid + 256*i; int r = u >> 3, sj = u & 7;
        cp16(bbase + r*ROWB + sj*16, Bp + (size_t)r*NH + k0 + sj*8, 16u);
    }
    CP_COMMIT();
}

// ---------------- fragment load for one k16-step ----------------
__device__ __forceinline__ void ldfrags(uint32_t As, uint32_t Bs, int ks,
        int arow, uint32_t acol, int brow, uint32_t bcol,
        uint32_t af[4][4], uint32_t bf[2][4]) {
    uint32_t kb = (uint32_t)(ks*32);
    #pragma unroll
    for (int mt = 0; mt < 4; mt++)
        ldsm4(af[mt], As + (uint32_t)(arow + mt*16)*ROWB + kb + acol);
    #pragma unroll
    for (int p = 0; p < 2; p++)
        ldsm4(bf[p], Bs + (uint32_t)(brow + p*16)*ROWB + kb + bcol);
}

// ---------------- chunk compute: register double-buffered fragments ----------------
// LDSM for ks+1 issues BEFORE the HMMAs of ks, overlapping LSU with tensor pipe.
__device__ __forceinline__ void chunk_mma(uint32_t ab, int buf,
        int wm, int wn, int lane, float acc[4][4][4]) {
    uint32_t As = ab + buf*STGB;
    uint32_t Bs = As + ABYTES;
    int l7 = lane & 7;
    int arow = wm*64 + ((lane>>3)&1)*8 + l7;
    uint32_t acol = (uint32_t)((lane>>4)*16);
    int brow = wn*32 + ((lane>>4)&1)*8 + l7;
    uint32_t bcol = (uint32_t)(((lane>>3)&1)*16);

    uint32_t af[2][4][4], bf[2][2][4];
    ldfrags(As, Bs, 0, arow, acol, brow, bcol, af[0], bf[0]);
    #pragma unroll
    for (int ks = 0; ks < 4; ks++) {
        int cur = ks & 1, nxt = cur ^ 1;
        if (ks < 3)
            ldfrags(As, Bs, ks+1, arow, acol, brow, bcol, af[nxt], bf[nxt]);
        #pragma unroll
        for (int mt = 0; mt < 4; mt++)
            #pragma unroll
            for (int nt = 0; nt < 4; nt++)
                mma_f16(acc[mt][nt], af[cur][mt], &bf[cur][nt>>1][(nt&1)*2]);
    }
}

// ---------------- expert offset ----------------
__device__ __forceinline__ int expert_off(int e) {
    int s = 0;
    #pragma unroll
    for (int k = 0; k < NE; k++) if (k < e) s += g_cnt[k];
    return s;
}

// ---------------- GEMM1: h = h16(gelu(x @ W1 + b1)) ----------------
__global__ __launch_bounds__(256, 2) void gemm1_mma(const float* __restrict__ b1) {
    extern __shared__ char smem[];
    int e = blockIdx.z;
    int cnt = g_cnt[e];
    int m0 = blockIdx.y * TM;
    if (m0 >= cnt) return;
    int n0 = blockIdx.x * TN;
    int tid = threadIdx.x;
    int lane = tid & 31;
    int wm = (tid >> 5) & 1, wn = tid >> 6;
    uint32_t ab = smem_u32(smem) + SOFF;
    int* rowpr = (int*)smem;
    __shared__ int s_base;
    if (tid < TM) {
        int m = m0 + tid;
        rowpr[tid] = (m < cnt) ? g_list[e][m] : -1;
    }
    if (tid == 0) s_base = expert_off(e) + m0;
    __syncthreads();

    const __half* Bp = g_W1t + ((size_t)e*NH + (size_t)n0)*ND;
    const int T = ND / KC;  // 16

    float acc[4][4][4];
    #pragma unroll
    for (int a = 0; a < 4; a++)
        #pragma unroll
        for (int b = 0; b < 4; b++)
            #pragma unroll
            for (int c = 0; c < 4; c++) acc[a][b][c] = 0.f;

    for (int s = 0; s < NSTG; s++) g1_load(ab, s, Bp, rowpr, tid);

    for (int t = 0; t < T; t++) {
        int buf = t % NSTG;
        if (t + NSTG <= T) CP_WAIT2(); else CP_WAIT0();
        __syncthreads();
        chunk_mma(ab, buf, wm, wn, lane, acc);
        __syncthreads();
        if (t + NSTG < T) g1_load(ab, t + NSTG, Bp, rowpr, tid);
    }

    int base_m = s_base;
    const float* bb = b1 + (size_t)e*NH + n0;
    #pragma unroll
    for (int mt = 0; mt < 4; mt++) {
        int r0 = wm*64 + mt*16 + (lane >> 2);
        #pragma unroll
        for (int half = 0; half < 2; half++) {
            int r = r0 + half*8;
            int pr = rowpr[r];
            if (pr < 0) continue;
            __half* hp = g_h + (size_t)(base_m + r)*NH + n0;
            #pragma unroll
            for (int nt = 0; nt < 4; nt++) {
                int cc = wn*32 + nt*8 + 2*(lane & 3);
                float v0 = acc[mt][nt][half*2+0] + bb[cc];
                float v1 = acc[mt][nt][half*2+1] + bb[cc+1];
                __half2 o = __floats2half2_rn(v0 * normcdff(v0), v1 * normcdff(v1));
                *(__half2*)(hp + cc) = o;
            }
        }
    }
}

// ---------------- GEMM2: y = h @ W2 + b2 ----------------
__global__ __launch_bounds__(256, 2) void gemm2_mma(const float* __restrict__ b2) {
    extern __shared__ char smem[];
    int e = blockIdx.z;
    int cnt = g_cnt[e];
    int m0 = blockIdx.y * TM;
    if (m0 >= cnt) return;
    int n0 = blockIdx.x * TN;
    int tid = threadIdx.x;
    int lane = tid & 31;
    int wm = (tid >> 5) & 1, wn = tid >> 6;
    uint32_t ab = smem_u32(smem) + SOFF;
    int* rowpr = (int*)smem;
    __shared__ int s_base;
    if (tid < TM) {
        int m = m0 + tid;
        rowpr[tid] = (m < cnt) ? g_list[e][m] : -1;
    }
    if (tid == 0) s_base = expert_off(e) + m0;
    __syncthreads();

    int base_m = s_base;
    int nvalid = cnt - m0; if (nvalid > TM) nvalid = TM;
    const __half* Bp = g_W2t + ((size_t)e*ND + (size_t)n0)*NH;
    const int T = NH / KC;  // 64

    float acc[4][4][4];
    #pragma unroll
    for (int a = 0; a < 4; a++)
        #pragma unroll
        for (int b = 0; b < 4; b++)
            #pragma unroll
            for (int c = 0; c < 4; c++) acc[a][b][c] = 0.f;

    for (int s = 0; s < NSTG; s++) g2_load(ab, s, base_m, nvalid, Bp, tid);

    for (int t = 0; t < T; t++) {
        int buf = t % NSTG;
        if (t + NSTG <= T) CP_WAIT2(); else CP_WAIT0();
        __syncthreads();
        chunk_mma(ab, buf, wm, wn, lane, acc);
        __syncthreads();
        if (t + NSTG < T) g2_load(ab, t + NSTG, base_m, nvalid, Bp, tid);
    }

    const float* bb = b2 + (size_t)e*ND + n0;
    #pragma unroll
    for (int mt = 0; mt < 4; mt++) {
        int r0 = wm*64 + mt*16 + (lane >> 2);
        #pragma unroll
        for (int half = 0; half < 2; half++) {
            int r = r0 + half*8;
            int pr = rowpr[r];
            if (pr < 0) continue;
            float* yp = g_y + (size_t)pr*ND + n0;
            #pragma unroll
            for (int nt = 0; nt < 4; nt++) {
                int cc = wn*32 + nt*8 + 2*(lane & 3);
                float2 o;
                o.x = acc[mt][nt][half*2+0] + bb[cc];
                o.y = acc[mt][nt][half*2+1] + bb[cc+1];
                *(float2*)(yp + cc) = o;
            }
        }
    }
}

// ---------------- combine ----------------
__global__ __launch_bounds__(256) void combine_kernel(float* __restrict__ out) {
    size_t i4 = (size_t)blockIdx.x*256 + threadIdx.x;
    size_t base = i4 * 4;
    int t = (int)(base >> 10);
    int d = (int)(base & (ND-1));
    float g0 = g_gate[2*t], g1 = g_gate[2*t+1];
    float4 y0 = *(const float4*)(g_y + (size_t)(2*t)*ND + d);
    float4 y1 = *(const float4*)(g_y + (size_t)(2*t+1)*ND + d);
    float4 o;
    o.x = g0*y0.x + g1*y1.x;
    o.y = g0*y0.y + g1*y1.y;
    o.z = g0*y0.z + g1*y1.z;
    o.w = g0*y0.w + g1*y1.w;
    *(float4*)(out + base) = o;
}

// ---------------- finalize aux losses ----------------
__global__ void finalize_kernel(float* __restrict__ out) {
    const float invT = 1.f/(float)NTOK;
    float lb = 0.f;
    #pragma unroll
    for (int e = 0; e < NE; e++) {
        float im = g_imp[e]*invT - 1.f/NE;
        lb += im*im;
    }
    lb *= 1.f/NE;
    float rz  = g_rz  * invT;
    float ent = g_ent * invT;
    size_t o = (size_t)NTOK*ND;
    out[o+0] = lb;
    out[o+1] = rz;
    out[o+2] = ent;
    out[o+3] = lb + 0.001f*rz - 0.001f*ent;
}

// ---------------- launch ----------------
extern "C" void kernel_launch(void* const* d_in, const int* in_sizes, int n_in,
                              void* d_out, int out_size) {
    const float* x      = (const float*)d_in[0];
    const float* ctx    = (const float*)d_in[1];
    const float* qual   = (const float*)d_in[2];
    const float* rn_g   = (const float*)d_in[3];
    const float* rn_b   = (const float*)d_in[4];
    const float* cn_g   = (const float*)d_in[5];
    const float* cn_b   = (const float*)d_in[6];
    const float* ctx_W  = (const float*)d_in[7];
    const float* ctx_b  = (const float*)d_in[8];
    const float* q_W    = (const float*)d_in[9];
    const float* q_b    = (const float*)d_in[10];
    const float* r_W    = (const float*)d_in[11];
    const float* r_b    = (const float*)d_in[12];
    const float* temp   = (const float*)d_in[13];
    const float* W1     = (const float*)d_in[14];
    const float* b1     = (const float*)d_in[15];
    const float* W2     = (const float*)d_in[16];
    const float* b2     = (const float*)d_in[17];
    float* out = (float*)d_out;

    cudaFuncSetAttribute(gemm1_mma, cudaFuncAttributeMaxDynamicSharedMemorySize, DSMEM);
    cudaFuncSetAttribute(gemm2_mma, cudaFuncAttributeMaxDynamicSharedMemorySize, DSMEM);

    // our 4th launch is the one ncu profiles -> keep gemm1 there
    prep_all<<<ND+1, 256>>>(ctx_W, r_W, ctx_b, q_W, q_b, r_b);           // 1
    transpose_h<<<dim3(NH/32, ND/32, NE), dim3(32, 8)>>>(W1, ND, NH, 0); // 2
    router_kernel<<<NTOK/8, 256>>>(x, ctx, qual, rn_g, rn_b, cn_g, cn_b, r_W, temp); // 3
    gemm1_mma<<<dim3(NH/TN, NPAIR/TM, NE), 256, DSMEM>>>(b1);            // 4 <- profiled
    transpose_h<<<dim3(ND/32, NH/32, NE), dim3(32, 8)>>>(W2, NH, ND, 1); // 5
    gemm2_mma<<<dim3(ND/TN, NPAIR/TM, NE), 256, DSMEM>>>(b2);            // 6
    combine_kernel<<<(NTOK*ND)/(256*4), 256>>>(out);                     // 7
    finalize_kernel<<<1, 1>>>(out);                                      // 8
}

// round 13
// speedup vs baseline: 1.1866x; 1.0058x over previous
#include <cuda_runtime.h>
#include <cuda_fp16.h>
#include <math.h>
#include <stdint.h>

#define NB 4
#define NS 2048
#define ND 1024
#define NH 4096
#define NE 8
#define NTOK (NB*NS)      /* 8192 tokens */
#define NPAIR (NTOK*2)    /* 16384 (token,expert) pairs */

#define TM 128
#define TN 128
#define KC 64               /* K per stage (64 halfs = 128 B rows) */
#define NSTG 3
#define ROWB 144            /* padded row: 128 B data + 16 B pad */
#define ABYTES (128*ROWB)   /* 18432 B per matrix per stage */
#define STGB (2*ABYTES)
#define SOFF 512
#define DSMEM (SOFF + NSTG*STGB)   /* 111104 B -> 2 CTAs/SM */

// ---------------- device scratch (static allocations only) ----------------
__device__ float g_M[ND*NE];
__device__ float g_cvec[NE];
__device__ float g_qv[NE];
__device__ int   g_cnt[NE];
__device__ int   g_list[NE][NTOK];
__device__ float g_gate[NPAIR];
__device__ __half g_xh[(size_t)NTOK*ND];      // fp16 x (written by router)
__device__ __half g_W1t[(size_t)NE*NH*ND];    // W1^T  [e][n][k], fp16
__device__ __half g_W2t[(size_t)NE*ND*NH];    // W2^T  [e][n][k], fp16
__device__ __half g_h[(size_t)NPAIR*NH];      // hidden acts, fp16
__device__ float g_imp[NE];
__device__ float g_rz;
__device__ float g_ent;

// ---------------- helpers ----------------
__device__ __forceinline__ uint32_t smem_u32(const void* p) {
    uint32_t a;
    asm("{ .reg .u64 t; cvta.to.shared.u64 t, %1; cvt.u32.u64 %0, t; }"
        : "=r"(a) : "l"(p));
    return a;
}
__device__ __forceinline__ void cp16(uint32_t dst, const void* src, uint32_t bytes) {
    asm volatile("cp.async.cg.shared.global [%0], [%1], 16, %2;\n"
                 :: "r"(dst), "l"(src), "r"(bytes) : "memory");
}
#define CP_COMMIT() asm volatile("cp.async.commit_group;\n" ::: "memory")
#define CP_WAIT2()  asm volatile("cp.async.wait_group 2;\n" ::: "memory")
#define CP_WAIT0()  asm volatile("cp.async.wait_group 0;\n" ::: "memory")

__device__ __forceinline__ void mma_f16(float* c, const uint32_t* a, const uint32_t* b) {
    asm volatile("mma.sync.aligned.m16n8k16.row.col.f32.f16.f16.f32 "
        "{%0,%1,%2,%3}, {%4,%5,%6,%7}, {%8,%9}, {%0,%1,%2,%3};"
        : "+f"(c[0]), "+f"(c[1]), "+f"(c[2]), "+f"(c[3])
        : "r"(a[0]), "r"(a[1]), "r"(a[2]), "r"(a[3]), "r"(b[0]), "r"(b[1]));
}
__device__ __forceinline__ void ldsm4(uint32_t* r, uint32_t a) {
    asm volatile("ldmatrix.sync.aligned.m8n8.x4.shared.b16 {%0,%1,%2,%3}, [%4];"
        : "=r"(r[0]), "=r"(r[1]), "=r"(r[2]), "=r"(r[3]) : "r"(a));
}

// ---------------- fused prep: init + small vectors + prep_M + BOTH transposes ----
__device__ __forceinline__ float blk_sum(float v, float* sred) {
    int tid = threadIdx.x;
    sred[tid] = v;
    __syncthreads();
    #pragma unroll
    for (int o = 128; o > 0; o >>= 1) {
        if (tid < o) sred[tid] += sred[tid + o];
        __syncthreads();
    }
    float r = sred[0];
    __syncthreads();
    return r;
}

#define PREP_BLKS (ND+1)
#define T1_BLKS (NE*(ND/32)*(NH/32))   /* 32768 */
#define T2_BLKS T1_BLKS

__global__ __launch_bounds__(256) void prep_fused(
        const float* __restrict__ ctx_W, const float* __restrict__ r_W,
        const float* __restrict__ ctx_b, const float* __restrict__ q_W,
        const float* __restrict__ q_b,  const float* __restrict__ r_b,
        const float* __restrict__ W1,   const float* __restrict__ W2) {
    int b = blockIdx.x;
    int tid = threadIdx.x;
    if (b < PREP_BLKS) {
        __shared__ float sred[256];
        if (b == 0) {
            if (tid < NE) { g_cnt[tid] = 0; g_imp[tid] = 0.f; }
            if (tid == 0) { g_rz = 0.f; g_ent = 0.f; }
            float pc[NE], pq[NE];
            #pragma unroll
            for (int e = 0; e < NE; e++) { pc[e] = 0.f; pq[e] = 0.f; }
            for (int d = tid; d < ND; d += 256) {
                float cb = ctx_b[d] + q_b[d];
                float qw = q_W[d];
                #pragma unroll
                for (int e = 0; e < NE; e++) {
                    pc[e] += cb * r_W[d*NE + e];
                    pq[e] += qw * r_W[d*NE + e];
                }
            }
            #pragma unroll
            for (int e = 0; e < NE; e++) {
                float vc = blk_sum(pc[e], sred);
                float vq = blk_sum(pq[e], sred);
                if (tid == 0) { g_cvec[e] = vc + r_b[e]; g_qv[e] = vq; }
            }
        } else {
            int j = b - 1;
            float part[NE];
            #pragma unroll
            for (int e = 0; e < NE; e++) part[e] = 0.f;
            for (int d = tid; d < ND; d += 256) {
                float w = ctx_W[(size_t)j*ND + d];
                #pragma unroll
                for (int e = 0; e < NE; e++) part[e] += w * r_W[d*NE + e];
            }
            #pragma unroll
            for (int e = 0; e < NE; e++) {
                float v = blk_sum(part[e], sred);
                if (tid == 0) g_M[j*NE + e] = v;
            }
        }
        return;
    }
    // transpose work
    __shared__ float t[32][33];
    const float* S;
    __half* D;
    int R, C, c0, r0;
    if (b < PREP_BLKS + T1_BLKS) {
        int i = b - PREP_BLKS;
        int e = i >> 12;           // / 4096
        int rem = i & 4095;        // 128 cblk x 32 rblk  (R=ND, C=NH)
        R = ND; C = NH;
        c0 = (rem & 127) * 32;
        r0 = (rem >> 7) * 32;
        S = W1 + (size_t)e*ND*NH;
        D = g_W1t + (size_t)e*ND*NH;
    } else {
        int i = b - PREP_BLKS - T1_BLKS;
        int e = i >> 12;
        int rem = i & 4095;        // 32 cblk x 128 rblk  (R=NH, C=ND)
        R = NH; C = ND;
        c0 = (rem & 31) * 32;
        r0 = (rem >> 5) * 32;
        S = W2 + (size_t)e*NH*ND;
        D = g_W2t + (size_t)e*NH*ND;
    }
    int tx = tid & 31, ty = tid >> 5;
    #pragma unroll
    for (int i = 0; i < 32; i += 8)
        t[ty+i][tx] = S[(size_t)(r0+ty+i)*C + c0+tx];
    __syncthreads();
    #pragma unroll
    for (int i = 0; i < 32; i += 8)
        D[(size_t)(c0+ty+i)*R + r0+tx] = __float2half(t[tx][ty+i]);
}

// ---------------- router: one warp per token; also zeroes out[] ----------------
__global__ __launch_bounds__(256) void router_kernel(
        const float* __restrict__ x, const float* __restrict__ ctx,
        const float* __restrict__ quality,
        const float* __restrict__ rn_g, const float* __restrict__ rn_b,
        const float* __restrict__ cn_g, const float* __restrict__ cn_b,
        const float* __restrict__ r_W, const float* __restrict__ temp_p,
        float* __restrict__ out) {
    int wid = threadIdx.x >> 5, lane = threadIdx.x & 31;
    int t = blockIdx.x*8 + wid;

    // zero output rows for this token (gemm2 accumulates atomically)
    {
        float4 z = make_float4(0.f,0.f,0.f,0.f);
        float4* op = (float4*)(out + (size_t)t*ND);
        #pragma unroll
        for (int i = 0; i < 8; i++) op[lane + 32*i] = z;
    }

    const float4* xr = (const float4*)(x   + (size_t)t*ND);
    const float4* cr = (const float4*)(ctx + (size_t)t*ND);
    float4 xv[8], cv[8];
    #pragma unroll
    for (int i = 0; i < 8; i++) { xv[i] = xr[lane + 32*i]; cv[i] = cr[lane + 32*i]; }

    #pragma unroll
    for (int i = 0; i < 8; i++) {
        __half2 h0 = __floats2half2_rn(xv[i].x, xv[i].y);
        __half2 h1 = __floats2half2_rn(xv[i].z, xv[i].w);
        uint2 o = make_uint2(*(uint32_t*)&h0, *(uint32_t*)&h1);
        *(uint2*)(g_xh + (size_t)t*ND + (lane + 32*i)*4) = o;
    }

    float sx=0.f, sxx=0.f, sc=0.f, scc=0.f;
    #pragma unroll
    for (int i = 0; i < 8; i++) {
        sx  += xv[i].x + xv[i].y + xv[i].z + xv[i].w;
        sxx += xv[i].x*xv[i].x + xv[i].y*xv[i].y + xv[i].z*xv[i].z + xv[i].w*xv[i].w;
        sc  += cv[i].x + cv[i].y + cv[i].z + cv[i].w;
        scc += cv[i].x*cv[i].x + cv[i].y*cv[i].y + cv[i].z*cv[i].z + cv[i].w*cv[i].w;
    }
    #pragma unroll
    for (int o = 16; o; o >>= 1) {
        sx  += __shfl_xor_sync(0xFFFFFFFFu, sx,  o);
        sxx += __shfl_xor_sync(0xFFFFFFFFu, sxx, o);
        sc  += __shfl_xor_sync(0xFFFFFFFFu, sc,  o);
        scc += __shfl_xor_sync(0xFFFFFFFFu, scc, o);
    }
    float mu_x = sx*(1.f/ND), mu_c = sc*(1.f/ND);
    float rs_x = rsqrtf(sxx*(1.f/ND) - mu_x*mu_x + 1e-5f);
    float rs_c = rsqrtf(scc*(1.f/ND) - mu_c*mu_c + 1e-5f);

    float part[NE];
    #pragma unroll
    for (int e = 0; e < NE; e++) part[e] = 0.f;
    #pragma unroll
    for (int i = 0; i < 8; i++) {
        float xa[4] = {xv[i].x, xv[i].y, xv[i].z, xv[i].w};
        float ca[4] = {cv[i].x, cv[i].y, cv[i].z, cv[i].w};
        #pragma unroll
        for (int j = 0; j < 4; j++) {
            int d = (lane + 32*i)*4 + j;
            float nx = (xa[j]-mu_x)*rs_x*rn_g[d] + rn_b[d];
            float nc = (ca[j]-mu_c)*rs_c*cn_g[d] + cn_b[d];
            const float* rw = r_W + d*NE;
            const float* mm = g_M + d*NE;
            #pragma unroll
            for (int e = 0; e < NE; e++) part[e] += nx*rw[e] + nc*mm[e];
        }
    }
    #pragma unroll
    for (int e = 0; e < NE; e++)
        #pragma unroll
        for (int o = 16; o; o >>= 1)
            part[e] += __shfl_xor_sync(0xFFFFFFFFu, part[e], o);

    __shared__ float simp[8][NE];
    __shared__ float srz[8];
    __shared__ float sent[8];

    if (lane == 0) {
        float temp = fmaxf(temp_p[0], 0.25f);
        float q = quality[t / NS];
        float lg[NE];
        #pragma unroll
        for (int e = 0; e < NE; e++)
            lg[e] = (part[e] + g_cvec[e] + q*g_qv[e]) / temp;

        int i1 = 0;
        #pragma unroll
        for (int e = 1; e < NE; e++) if (lg[e] > lg[i1]) i1 = e;
        int i2 = (i1 == 0) ? 1 : 0;
        #pragma unroll
        for (int e = 0; e < NE; e++) {
            if (e == i1 || e == i2) continue;
            if (lg[e] > lg[i2]) i2 = e;
        }

        float mx = lg[0];
        #pragma unroll
        for (int e = 1; e < NE; e++) mx = fmaxf(mx, lg[e]);
        float se = 0.f;
        #pragma unroll
        for (int e = 0; e < NE; e++) se += expf(lg[e]-mx);
        float lse = mx + logf(se);
        float inv_se = 1.f/se;
        float ent = 0.f;
        #pragma unroll
        for (int e = 0; e < NE; e++) {
            float p = expf(lg[e]-mx)*inv_se;
            simp[wid][e] = p;
            ent -= p * (lg[e]-lse);
        }
        srz[wid]  = lse*lse;
        sent[wid] = ent;

        float ex = expf(lg[i2]-lg[i1]);
        float inv = 1.f/(1.f+ex);
        g_gate[2*t]   = inv;
        g_gate[2*t+1] = ex*inv;
        int p1 = atomicAdd(&g_cnt[i1], 1);
        g_list[i1][p1] = 2*t;
        int p2 = atomicAdd(&g_cnt[i2], 1);
        g_list[i2][p2] = 2*t+1;
    }
    __syncthreads();
    int tid = threadIdx.x;
    if (tid < NE) {
        float s = 0.f;
        #pragma unroll
        for (int w = 0; w < 8; w++) s += simp[w][tid];
        atomicAdd(&g_imp[tid], s);
    } else if (tid == 8) {
        float s = 0.f;
        #pragma unroll
        for (int w = 0; w < 8; w++) s += srz[w];
        atomicAdd(&g_rz, s);
    } else if (tid == 9) {
        float s = 0.f;
        #pragma unroll
        for (int w = 0; w < 8; w++) s += sent[w];
        atomicAdd(&g_ent, s);
    }
}

// ---------------- stage loaders (fp16 rows: 128 B data + 16 B pad) ----------------
__device__ __forceinline__ void g1_load(uint32_t ab, int s,
        const __half* __restrict__ Bp, const int* rowpr, int tid) {
    int buf = s % NSTG;
    int k0 = s * KC;
    uint32_t abase = ab + buf*STGB;
    uint32_t bbase = abase + ABYTES;
    #pragma unroll
    for (int i = 0; i < 4; i++) {
        int u = tid + 256*i; int r = u >> 3, sj = u & 7;
        int pr = rowpr[r];
        const __half* src = (pr >= 0) ? (g_xh + ((size_t)(pr >> 1))*ND + k0 + sj*8) : g_xh;
        cp16(abase + r*ROWB + sj*16, src, (pr >= 0) ? 16u : 0u);
    }
    #pragma unroll
    for (int i = 0; i < 4; i++) {
        int u = tid + 256*i; int r = u >> 3, sj = u & 7;
        cp16(bbase + r*ROWB + sj*16, Bp + (size_t)r*ND + k0 + sj*8, 16u);
    }
    CP_COMMIT();
}

__device__ __forceinline__ void g2_load(uint32_t ab, int s,
        int base_m, int nvalid, const __half* __restrict__ Bp, int tid) {
    int buf = s % NSTG;
    int k0 = s * KC;
    uint32_t abase = ab + buf*STGB;
    uint32_t bbase = abase + ABYTES;
    #pragma unroll
    for (int i = 0; i < 4; i++) {
        int u = tid + 256*i; int r = u >> 3, sj = u & 7;
        bool ok = (r < nvalid);
        const __half* src = g_h + (size_t)(base_m + (ok ? r : 0))*NH + k0 + sj*8;
        cp16(abase + r*ROWB + sj*16, src, ok ? 16u : 0u);
    }
    #pragma unroll
    for (int i = 0; i < 4; i++) {
        int u = tid + 256*i; int r = u >> 3, sj = u & 7;
        cp16(bbase + r*ROWB + sj*16, Bp + (size_t)r*NH + k0 + sj*8, 16u);
    }
    CP_COMMIT();
}

// ---------------- fragment load for one k16-step ----------------
__device__ __forceinline__ void ldfrags(uint32_t As, uint32_t Bs, int ks,
        int arow, uint32_t acol, int brow, uint32_t bcol,
        uint32_t af[4][4], uint32_t bf[2][4]) {
    uint32_t kb = (uint32_t)(ks*32);
    #pragma unroll
    for (int mt = 0; mt < 4; mt++)
        ldsm4(af[mt], As + (uint32_t)(arow + mt*16)*ROWB + kb + acol);
    #pragma unroll
    for (int p = 0; p < 2; p++)
        ldsm4(bf[p], Bs + (uint32_t)(brow + p*16)*ROWB + kb + bcol);
}

// ---------------- chunk compute: register double-buffered fragments ----------------
__device__ __forceinline__ void chunk_mma(uint32_t ab, int buf,
        int wm, int wn, int lane, float acc[4][4][4]) {
    uint32_t As = ab + buf*STGB;
    uint32_t Bs = As + ABYTES;
    int l7 = lane & 7;
    int arow = wm*64 + ((lane>>3)&1)*8 + l7;
    uint32_t acol = (uint32_t)((lane>>4)*16);
    int brow = wn*32 + ((lane>>4)&1)*8 + l7;
    uint32_t bcol = (uint32_t)(((lane>>3)&1)*16);

    uint32_t af[2][4][4], bf[2][2][4];
    ldfrags(As, Bs, 0, arow, acol, brow, bcol, af[0], bf[0]);
    #pragma unroll
    for (int ks = 0; ks < 4; ks++) {
        int cur = ks & 1, nxt = cur ^ 1;
        if (ks < 3)
            ldfrags(As, Bs, ks+1, arow, acol, brow, bcol, af[nxt], bf[nxt]);
        #pragma unroll
        for (int mt = 0; mt < 4; mt++)
            #pragma unroll
            for (int nt = 0; nt < 4; nt++)
                mma_f16(acc[mt][nt], af[cur][mt], &bf[cur][nt>>1][(nt&1)*2]);
    }
}

// ---------------- expert offset ----------------
__device__ __forceinline__ int expert_off(int e) {
    int s = 0;
    #pragma unroll
    for (int k = 0; k < NE; k++) if (k < e) s += g_cnt[k];
    return s;
}

// ---------------- GEMM1: h = h16(gelu(x @ W1 + b1)) ----------------
__global__ __launch_bounds__(256, 2) void gemm1_mma(const float* __restrict__ b1) {
    extern __shared__ char smem[];
    int e = blockIdx.z;
    int cnt = g_cnt[e];
    int m0 = blockIdx.y * TM;
    if (m0 >= cnt) return;
    int n0 = blockIdx.x * TN;
    int tid = threadIdx.x;
    int lane = tid & 31;
    int wm = (tid >> 5) & 1, wn = tid >> 6;
    uint32_t ab = smem_u32(smem) + SOFF;
    int* rowpr = (int*)smem;
    __shared__ int s_base;
    if (tid < TM) {
        int m = m0 + tid;
        rowpr[tid] = (m < cnt) ? g_list[e][m] : -1;
    }
    if (tid == 0) s_base = expert_off(e) + m0;
    __syncthreads();

    const __half* Bp = g_W1t + ((size_t)e*NH + (size_t)n0)*ND;
    const int T = ND / KC;  // 16

    float acc[4][4][4];
    #pragma unroll
    for (int a = 0; a < 4; a++)
        #pragma unroll
        for (int b = 0; b < 4; b++)
            #pragma unroll
            for (int c = 0; c < 4; c++) acc[a][b][c] = 0.f;

    for (int s = 0; s < NSTG; s++) g1_load(ab, s, Bp, rowpr, tid);

    for (int t = 0; t < T; t++) {
        int buf = t % NSTG;
        if (t + NSTG <= T) CP_WAIT2(); else CP_WAIT0();
        __syncthreads();
        chunk_mma(ab, buf, wm, wn, lane, acc);
        __syncthreads();
        if (t + NSTG < T) g1_load(ab, t + NSTG, Bp, rowpr, tid);
    }

    int base_m = s_base;
    const float* bb = b1 + (size_t)e*NH + n0;
    #pragma unroll
    for (int mt = 0; mt < 4; mt++) {
        int r0 = wm*64 + mt*16 + (lane >> 2);
        #pragma unroll
        for (int half = 0; half < 2; half++) {
            int r = r0 + half*8;
            int pr = rowpr[r];
            if (pr < 0) continue;
            __half* hp = g_h + (size_t)(base_m + r)*NH + n0;
            #pragma unroll
            for (int nt = 0; nt < 4; nt++) {
                int cc = wn*32 + nt*8 + 2*(lane & 3);
                float v0 = acc[mt][nt][half*2+0] + bb[cc];
                float v1 = acc[mt][nt][half*2+1] + bb[cc+1];
                __half2 o = __floats2half2_rn(v0 * normcdff(v0), v1 * normcdff(v1));
                *(__half2*)(hp + cc) = o;
            }
        }
    }
}

// ---------------- GEMM2 (fused gating + combine): out += gate * (h @ W2 + b2) ----
__global__ __launch_bounds__(256, 2) void gemm2_mma(const float* __restrict__ b2,
                                                    float* __restrict__ out) {
    extern __shared__ char smem[];
    int e = blockIdx.z;
    int cnt = g_cnt[e];
    int m0 = blockIdx.y * TM;
    if (m0 >= cnt) return;
    int n0 = blockIdx.x * TN;
    int tid = threadIdx.x;
    int lane = tid & 31;
    int wm = (tid >> 5) & 1, wn = tid >> 6;
    uint32_t ab = smem_u32(smem) + SOFF;
    int* rowpr = (int*)smem;
    __shared__ int s_base;
    if (tid < TM) {
        int m = m0 + tid;
        rowpr[tid] = (m < cnt) ? g_list[e][m] : -1;
    }
    if (tid == 0) s_base = expert_off(e) + m0;
    __syncthreads();

    int base_m = s_base;
    int nvalid = cnt - m0; if (nvalid > TM) nvalid = TM;
    const __half* Bp = g_W2t + ((size_t)e*ND + (size_t)n0)*NH;
    const int T = NH / KC;  // 64

    float acc[4][4][4];
    #pragma unroll
    for (int a = 0; a < 4; a++)
        #pragma unroll
        for (int b = 0; b < 4; b++)
            #pragma unroll
            for (int c = 0; c < 4; c++) acc[a][b][c] = 0.f;

    for (int s = 0; s < NSTG; s++) g2_load(ab, s, base_m, nvalid, Bp, tid);

    for (int t = 0; t < T; t++) {
        int buf = t % NSTG;
        if (t + NSTG <= T) CP_WAIT2(); else CP_WAIT0();
        __syncthreads();
        chunk_mma(ab, buf, wm, wn, lane, acc);
        __syncthreads();
        if (t + NSTG < T) g2_load(ab, t + NSTG, base_m, nvalid, Bp, tid);
    }

    const float* bb = b2 + (size_t)e*ND + n0;
    #pragma unroll
    for (int mt = 0; mt < 4; mt++) {
        int r0 = wm*64 + mt*16 + (lane >> 2);
        #pragma unroll
        for (int half = 0; half < 2; half++) {
            int r = r0 + half*8;
            int pr = rowpr[r];
            if (pr < 0) continue;
            float g = g_gate[pr];
            float* op = out + (size_t)(pr >> 1)*ND + n0;
            #pragma unroll
            for (int nt = 0; nt < 4; nt++) {
                int cc = wn*32 + nt*8 + 2*(lane & 3);
                atomicAdd(op + cc,     g * (acc[mt][nt][half*2+0] + bb[cc]));
                atomicAdd(op + cc + 1, g * (acc[mt][nt][half*2+1] + bb[cc+1]));
            }
        }
    }
}

// ---------------- finalize aux losses ----------------
__global__ void finalize_kernel(float* __restrict__ out) {
    const float invT = 1.f/(float)NTOK;
    float lb = 0.f;
    #pragma unroll
    for (int e = 0; e < NE; e++) {
        float im = g_imp[e]*invT - 1.f/NE;
        lb += im*im;
    }
    lb *= 1.f/NE;
    float rz  = g_rz  * invT;
    float ent = g_ent * invT;
    size_t o = (size_t)NTOK*ND;
    out[o+0] = lb;
    out[o+1] = rz;
    out[o+2] = ent;
    out[o+3] = lb + 0.001f*rz - 0.001f*ent;
}

// ---------------- launch ----------------
extern "C" void kernel_launch(void* const* d_in, const int* in_sizes, int n_in,
                              void* d_out, int out_size) {
    const float* x      = (const float*)d_in[0];
    const float* ctx    = (const float*)d_in[1];
    const float* qual   = (const float*)d_in[2];
    const float* rn_g   = (const float*)d_in[3];
    const float* rn_b   = (const float*)d_in[4];
    const float* cn_g   = (const float*)d_in[5];
    const float* cn_b   = (const float*)d_in[6];
    const float* ctx_W  = (const float*)d_in[7];
    const float* ctx_b  = (const float*)d_in[8];
    const float* q_W    = (const float*)d_in[9];
    const float* q_b    = (const float*)d_in[10];
    const float* r_W    = (const float*)d_in[11];
    const float* r_b    = (const float*)d_in[12];
    const float* temp   = (const float*)d_in[13];
    const float* W1     = (const float*)d_in[14];
    const float* b1     = (const float*)d_in[15];
    const float* W2     = (const float*)d_in[16];
    const float* b2     = (const float*)d_in[17];
    float* out = (float*)d_out;

    cudaFuncSetAttribute(gemm1_mma, cudaFuncAttributeMaxDynamicSharedMemorySize, DSMEM);
    cudaFuncSetAttribute(gemm2_mma, cudaFuncAttributeMaxDynamicSharedMemorySize, DSMEM);

    // our 4th launch is the one ncu profiles -> gemm2 this round
    prep_fused<<<PREP_BLKS + T1_BLKS + T2_BLKS, 256>>>(ctx_W, r_W, ctx_b, q_W,
                                                       q_b, r_b, W1, W2);    // 1
    router_kernel<<<NTOK/8, 256>>>(x, ctx, qual, rn_g, rn_b, cn_g, cn_b,
                                   r_W, temp, out);                          // 2
    gemm1_mma<<<dim3(NH/TN, NPAIR/TM, NE), 256, DSMEM>>>(b1);                // 3
    gemm2_mma<<<dim3(ND/TN, NPAIR/TM, NE), 256, DSMEM>>>(b2, out);           // 4 <- profiled
    finalize_kernel<<<1, 1>>>(out);                                          // 5
}

// round 14
// speedup vs baseline: 1.2023x; 1.0132x over previous
#include <cuda_runtime.h>
#include <cuda_fp16.h>
#include <math.h>
#include <stdint.h>

#define NB 4
#define NS 2048
#define ND 1024
#define NH 4096
#define NE 8
#define NTOK (NB*NS)      /* 8192 tokens */
#define NPAIR (NTOK*2)    /* 16384 (token,expert) pairs */

#define TM 128
#define TN 128
#define KC 64               /* K per stage (64 halfs = 128 B rows) */
#define NSTG 3
#define ROWB 144            /* padded row: 128 B data + 16 B pad */
#define ABYTES (128*ROWB)   /* 18432 B per matrix per stage */
#define STGB (2*ABYTES)
#define SOFF 512
#define DSMEM (SOFF + NSTG*STGB)   /* 111104 B -> 2 CTAs/SM */

// ---------------- device scratch (static allocations only) ----------------
__device__ float g_M[ND*NE];
__device__ float g_cvec[NE];
__device__ float g_qv[NE];
__device__ int   g_cnt[NE];
__device__ int   g_list[NE][NTOK];
__device__ float g_gate[NPAIR];
__device__ __half g_xh[(size_t)NTOK*ND];      // fp16 x (written by router)
__device__ __half g_W1t[(size_t)NE*NH*ND];    // W1^T  [e][n][k], fp16
__device__ __half g_W2t[(size_t)NE*ND*NH];    // W2^T  [e][n][k], fp16
__device__ __half g_h[(size_t)NPAIR*NH];      // hidden acts, fp16
__device__ float g_imp[NE];
__device__ float g_rz;
__device__ float g_ent;

// ---------------- helpers ----------------
__device__ __forceinline__ uint32_t smem_u32(const void* p) {
    uint32_t a;
    asm("{ .reg .u64 t; cvta.to.shared.u64 t, %1; cvt.u32.u64 %0, t; }"
        : "=r"(a) : "l"(p));
    return a;
}
__device__ __forceinline__ void cp16(uint32_t dst, const void* src, uint32_t bytes) {
    asm volatile("cp.async.cg.shared.global [%0], [%1], 16, %2;\n"
                 :: "r"(dst), "l"(src), "r"(bytes) : "memory");
}
#define CP_COMMIT() asm volatile("cp.async.commit_group;\n" ::: "memory")
#define CP_WAIT2()  asm volatile("cp.async.wait_group 2;\n" ::: "memory")
#define CP_WAIT0()  asm volatile("cp.async.wait_group 0;\n" ::: "memory")

__device__ __forceinline__ void mma_f16(float* c, const uint32_t* a, const uint32_t* b) {
    asm volatile("mma.sync.aligned.m16n8k16.row.col.f32.f16.f16.f32 "
        "{%0,%1,%2,%3}, {%4,%5,%6,%7}, {%8,%9}, {%0,%1,%2,%3};"
        : "+f"(c[0]), "+f"(c[1]), "+f"(c[2]), "+f"(c[3])
        : "r"(a[0]), "r"(a[1]), "r"(a[2]), "r"(a[3]), "r"(b[0]), "r"(b[1]));
}
__device__ __forceinline__ void ldsm4(uint32_t* r, uint32_t a) {
    asm volatile("ldmatrix.sync.aligned.m8n8.x4.shared.b16 {%0,%1,%2,%3}, [%4];"
        : "=r"(r[0]), "=r"(r[1]), "=r"(r[2]), "=r"(r[3]) : "r"(a));
}

// ---------------- fused prep: init + small vectors + prep_M + BOTH transposes ----
__device__ __forceinline__ float blk_sum(float v, float* sred) {
    int tid = threadIdx.x;
    sred[tid] = v;
    __syncthreads();
    #pragma unroll
    for (int o = 128; o > 0; o >>= 1) {
        if (tid < o) sred[tid] += sred[tid + o];
        __syncthreads();
    }
    float r = sred[0];
    __syncthreads();
    return r;
}

#define PREP_BLKS (ND+1)
#define T1_BLKS (NE*(ND/64)*(NH/32))   /* 16384 */
#define T2_BLKS (NE*(NH/64)*(ND/32))   /* 16384 */

__global__ __launch_bounds__(256) void prep_fused(
        const float* __restrict__ ctx_W, const float* __restrict__ r_W,
        const float* __restrict__ ctx_b, const float* __restrict__ q_W,
        const float* __restrict__ q_b,  const float* __restrict__ r_b,
        const float* __restrict__ W1,   const float* __restrict__ W2) {
    int b = blockIdx.x;
    int tid = threadIdx.x;
    if (b < PREP_BLKS) {
        __shared__ float sred[256];
        if (b == 0) {
            if (tid < NE) { g_cnt[tid] = 0; g_imp[tid] = 0.f; }
            if (tid == 0) { g_rz = 0.f; g_ent = 0.f; }
            float pc[NE], pq[NE];
            #pragma unroll
            for (int e = 0; e < NE; e++) { pc[e] = 0.f; pq[e] = 0.f; }
            for (int d = tid; d < ND; d += 256) {
                float cb = ctx_b[d] + q_b[d];
                float qw = q_W[d];
                #pragma unroll
                for (int e = 0; e < NE; e++) {
                    pc[e] += cb * r_W[d*NE + e];
                    pq[e] += qw * r_W[d*NE + e];
                }
            }
            #pragma unroll
            for (int e = 0; e < NE; e++) {
                float vc = blk_sum(pc[e], sred);
                float vq = blk_sum(pq[e], sred);
                if (tid == 0) { g_cvec[e] = vc + r_b[e]; g_qv[e] = vq; }
            }
        } else {
            int j = b - 1;
            float part[NE];
            #pragma unroll
            for (int e = 0; e < NE; e++) part[e] = 0.f;
            for (int d = tid; d < ND; d += 256) {
                float w = ctx_W[(size_t)j*ND + d];
                #pragma unroll
                for (int e = 0; e < NE; e++) part[e] += w * r_W[d*NE + e];
            }
            #pragma unroll
            for (int e = 0; e < NE; e++) {
                float v = blk_sum(part[e], sred);
                if (tid == 0) g_M[j*NE + e] = v;
            }
        }
        return;
    }
    // ---- transpose work: 64 S-rows x 32 S-cols per block ----
    // D rows get written as contiguous 128 B half2 runs (full warp sectors).
    __shared__ float t[64][33];
    const float* S;
    __half* D;
    int R, C, c0, r0;
    if (b < PREP_BLKS + T1_BLKS) {
        int i = b - PREP_BLKS;
        int e = i >> 11;            // / 2048
        int rem = i & 2047;         // 128 cblk x 16 rblk (R=ND=1024, C=NH)
        R = ND; C = NH;
        c0 = (rem & 127) * 32;
        r0 = (rem >> 7) * 64;
        S = W1 + (size_t)e*ND*NH;
        D = g_W1t + (size_t)e*ND*NH;
    } else {
        int i = b - PREP_BLKS - T1_BLKS;
        int e = i >> 11;
        int rem = i & 2047;         // 32 cblk x 64 rblk (R=NH=4096, C=ND)
        R = NH; C = ND;
        c0 = (rem & 31) * 32;
        r0 = (rem >> 5) * 64;
        S = W2 + (size_t)e*NH*ND;
        D = g_W2t + (size_t)e*NH*ND;
    }
    int lane = tid & 31, w = tid >> 5;   // 8 warps
    // load: warp w loads rows w*8..w*8+7, each row 32 floats (128 B coalesced)
    #pragma unroll
    for (int i = 0; i < 8; i++)
        t[w*8 + i][lane] = S[(size_t)(r0 + w*8 + i)*C + c0 + lane];
    __syncthreads();
    // store: warp w writes D rows c0+w, c0+w+8, c0+w+16, c0+w+24,
    // each row = 64 halfs = 128 B contiguous (half2 per lane)
    #pragma unroll
    for (int jj = 0; jj < 4; jj++) {
        int j = w + jj*8;
        __half2 v = __floats2half2_rn(t[2*lane][j], t[2*lane + 1][j]);
        *(__half2*)(D + (size_t)(c0 + j)*R + r0 + 2*lane) = v;
    }
}

// ---------------- router: one warp per token; also zeroes out[] ----------------
__global__ __launch_bounds__(256) void router_kernel(
        const float* __restrict__ x, const float* __restrict__ ctx,
        const float* __restrict__ quality,
        const float* __restrict__ rn_g, const float* __restrict__ rn_b,
        const float* __restrict__ cn_g, const float* __restrict__ cn_b,
        const float* __restrict__ r_W, const float* __restrict__ temp_p,
        float* __restrict__ out) {
    int wid = threadIdx.x >> 5, lane = threadIdx.x & 31;
    int t = blockIdx.x*8 + wid;

    {
        float4 z = make_float4(0.f,0.f,0.f,0.f);
        float4* op = (float4*)(out + (size_t)t*ND);
        #pragma unroll
        for (int i = 0; i < 8; i++) op[lane + 32*i] = z;
    }

    const float4* xr = (const float4*)(x   + (size_t)t*ND);
    const float4* cr = (const float4*)(ctx + (size_t)t*ND);
    float4 xv[8], cv[8];
    #pragma unroll
    for (int i = 0; i < 8; i++) { xv[i] = xr[lane + 32*i]; cv[i] = cr[lane + 32*i]; }

    #pragma unroll
    for (int i = 0; i < 8; i++) {
        __half2 h0 = __floats2half2_rn(xv[i].x, xv[i].y);
        __half2 h1 = __floats2half2_rn(xv[i].z, xv[i].w);
        uint2 o = make_uint2(*(uint32_t*)&h0, *(uint32_t*)&h1);
        *(uint2*)(g_xh + (size_t)t*ND + (lane + 32*i)*4) = o;
    }

    float sx=0.f, sxx=0.f, sc=0.f, scc=0.f;
    #pragma unroll
    for (int i = 0; i < 8; i++) {
        sx  += xv[i].x + xv[i].y + xv[i].z + xv[i].w;
        sxx += xv[i].x*xv[i].x + xv[i].y*xv[i].y + xv[i].z*xv[i].z + xv[i].w*xv[i].w;
        sc  += cv[i].x + cv[i].y + cv[i].z + cv[i].w;
        scc += cv[i].x*cv[i].x + cv[i].y*cv[i].y + cv[i].z*cv[i].z + cv[i].w*cv[i].w;
    }
    #pragma unroll
    for (int o = 16; o; o >>= 1) {
        sx  += __shfl_xor_sync(0xFFFFFFFFu, sx,  o);
        sxx += __shfl_xor_sync(0xFFFFFFFFu, sxx, o);
        sc  += __shfl_xor_sync(0xFFFFFFFFu, sc,  o);
        scc += __shfl_xor_sync(0xFFFFFFFFu, scc, o);
    }
    float mu_x = sx*(1.f/ND), mu_c = sc*(1.f/ND);
    float rs_x = rsqrtf(sxx*(1.f/ND) - mu_x*mu_x + 1e-5f);
    float rs_c = rsqrtf(scc*(1.f/ND) - mu_c*mu_c + 1e-5f);

    float part[NE];
    #pragma unroll
    for (int e = 0; e < NE; e++) part[e] = 0.f;
    #pragma unroll
    for (int i = 0; i < 8; i++) {
        float xa[4] = {xv[i].x, xv[i].y, xv[i].z, xv[i].w};
        float ca[4] = {cv[i].x, cv[i].y, cv[i].z, cv[i].w};
        #pragma unroll
        for (int j = 0; j < 4; j++) {
            int d = (lane + 32*i)*4 + j;
            float nx = (xa[j]-mu_x)*rs_x*rn_g[d] + rn_b[d];
            float nc = (ca[j]-mu_c)*rs_c*cn_g[d] + cn_b[d];
            const float* rw = r_W + d*NE;
            const float* mm = g_M + d*NE;
            #pragma unroll
            for (int e = 0; e < NE; e++) part[e] += nx*rw[e] + nc*mm[e];
        }
    }
    #pragma unroll
    for (int e = 0; e < NE; e++)
        #pragma unroll
        for (int o = 16; o; o >>= 1)
            part[e] += __shfl_xor_sync(0xFFFFFFFFu, part[e], o);

    __shared__ float simp[8][NE];
    __shared__ float srz[8];
    __shared__ float sent[8];

    if (lane == 0) {
        float temp = fmaxf(temp_p[0], 0.25f);
        float q = quality[t / NS];
        float lg[NE];
        #pragma unroll
        for (int e = 0; e < NE; e++)
            lg[e] = (part[e] + g_cvec[e] + q*g_qv[e]) / temp;

        int i1 = 0;
        #pragma unroll
        for (int e = 1; e < NE; e++) if (lg[e] > lg[i1]) i1 = e;
        int i2 = (i1 == 0) ? 1 : 0;
        #pragma unroll
        for (int e = 0; e < NE; e++) {
            if (e == i1 || e == i2) continue;
            if (lg[e] > lg[i2]) i2 = e;
        }

        float mx = lg[0];
        #pragma unroll
        for (int e = 1; e < NE; e++) mx = fmaxf(mx, lg[e]);
        float se = 0.f;
        #pragma unroll
        for (int e = 0; e < NE; e++) se += expf(lg[e]-mx);
        float lse = mx + logf(se);
        float inv_se = 1.f/se;
        float ent = 0.f;
        #pragma unroll
        for (int e = 0; e < NE; e++) {
            float p = expf(lg[e]-mx)*inv_se;
            simp[wid][e] = p;
            ent -= p * (lg[e]-lse);
        }
        srz[wid]  = lse*lse;
        sent[wid] = ent;

        float ex = expf(lg[i2]-lg[i1]);
        float inv = 1.f/(1.f+ex);
        g_gate[2*t]   = inv;
        g_gate[2*t+1] = ex*inv;
        int p1 = atomicAdd(&g_cnt[i1], 1);
        g_list[i1][p1] = 2*t;
        int p2 = atomicAdd(&g_cnt[i2], 1);
        g_list[i2][p2] = 2*t+1;
    }
    __syncthreads();
    int tid = threadIdx.x;
    if (tid < NE) {
        float s = 0.f;
        #pragma unroll
        for (int w = 0; w < 8; w++) s += simp[w][tid];
        atomicAdd(&g_imp[tid], s);
    } else if (tid == 8) {
        float s = 0.f;
        #pragma unroll
        for (int w = 0; w < 8; w++) s += srz[w];
        atomicAdd(&g_rz, s);
    } else if (tid == 9) {
        float s = 0.f;
        #pragma unroll
        for (int w = 0; w < 8; w++) s += sent[w];
        atomicAdd(&g_ent, s);
    }
}

// ---------------- stage loaders (fp16 rows: 128 B data + 16 B pad) ----------------
__device__ __forceinline__ void g1_load(uint32_t ab, int s,
        const __half* __restrict__ Bp, const int* rowpr, int tid) {
    int buf = s % NSTG;
    int k0 = s * KC;
    uint32_t abase = ab + buf*STGB;
    uint32_t bbase = abase + ABYTES;
    #pragma unroll
    for (int i = 0; i < 4; i++) {
        int u = tid + 256*i; int r = u >> 3, sj = u & 7;
        int pr = rowpr[r];
        const __half* src = (pr >= 0) ? (g_xh + ((size_t)(pr >> 1))*ND + k0 + sj*8) : g_xh;
        cp16(abase + r*ROWB + sj*16, src, (pr >= 0) ? 16u : 0u);
    }
    #pragma unroll
    for (int i = 0; i < 4; i++) {
        int u = tid + 256*i; int r = u >> 3, sj = u & 7;
        cp16(bbase + r*ROWB + sj*16, Bp + (size_t)r*ND + k0 + sj*8, 16u);
    }
    CP_COMMIT();
}

__device__ __forceinline__ void g2_load(uint32_t ab, int s,
        int base_m, int nvalid, const __half* __restrict__ Bp, int tid) {
    int buf = s % NSTG;
    int k0 = s * KC;
    uint32_t abase = ab + buf*STGB;
    uint32_t bbase = abase + ABYTES;
    #pragma unroll
    for (int i = 0; i < 4; i++) {
        int u = tid + 256*i; int r = u >> 3, sj = u & 7;
        bool ok = (r < nvalid);
        const __half* src = g_h + (size_t)(base_m + (ok ? r : 0))*NH + k0 + sj*8;
        cp16(abase + r*ROWB + sj*16, src, ok ? 16u : 0u);
    }
    #pragma unroll
    for (int i = 0; i < 4; i++) {
        int u = tid + 256*i; int r = u >> 3, sj = u & 7;
        cp16(bbase + r*ROWB + sj*16, Bp + (size_t)r*NH + k0 + sj*8, 16u);
    }
    CP_COMMIT();
}

// ---------------- fragment load for one k16-step ----------------
__device__ __forceinline__ void ldfrags(uint32_t As, uint32_t Bs, int ks,
        int arow, uint32_t acol, int brow, uint32_t bcol,
        uint32_t af[4][4], uint32_t bf[2][4]) {
    uint32_t kb = (uint32_t)(ks*32);
    #pragma unroll
    for (int mt = 0; mt < 4; mt++)
        ldsm4(af[mt], As + (uint32_t)(arow + mt*16)*ROWB + kb + acol);
    #pragma unroll
    for (int p = 0; p < 2; p++)
        ldsm4(bf[p], Bs + (uint32_t)(brow + p*16)*ROWB + kb + bcol);
}

// ---------------- chunk compute: register double-buffered fragments ----------------
__device__ __forceinline__ void chunk_mma(uint32_t ab, int buf,
        int wm, int wn, int lane, float acc[4][4][4]) {
    uint32_t As = ab + buf*STGB;
    uint32_t Bs = As + ABYTES;
    int l7 = lane & 7;
    int arow = wm*64 + ((lane>>3)&1)*8 + l7;
    uint32_t acol = (uint32_t)((lane>>4)*16);
    int brow = wn*32 + ((lane>>4)&1)*8 + l7;
    uint32_t bcol = (uint32_t)(((lane>>3)&1)*16);

    uint32_t af[2][4][4], bf[2][2][4];
    ldfrags(As, Bs, 0, arow, acol, brow, bcol, af[0], bf[0]);
    #pragma unroll
    for (int ks = 0; ks < 4; ks++) {
        int cur = ks & 1, nxt = cur ^ 1;
        if (ks < 3)
            ldfrags(As, Bs, ks+1, arow, acol, brow, bcol, af[nxt], bf[nxt]);
        #pragma unroll
        for (int mt = 0; mt < 4; mt++)
            #pragma unroll
            for (int nt = 0; nt < 4; nt++)
                mma_f16(acc[mt][nt], af[cur][mt], &bf[cur][nt>>1][(nt&1)*2]);
    }
}

// ---------------- expert offset ----------------
__device__ __forceinline__ int expert_off(int e) {
    int s = 0;
    #pragma unroll
    for (int k = 0; k < NE; k++) if (k < e) s += g_cnt[k];
    return s;
}

// ---------------- GEMM1: h = h16(gelu(x @ W1 + b1)) ----------------
__global__ __launch_bounds__(256, 2) void gemm1_mma(const float* __restrict__ b1) {
    extern __shared__ char smem[];
    int e = blockIdx.z;
    int cnt = g_cnt[e];
    int m0 = blockIdx.y * TM;
    if (m0 >= cnt) return;
    int n0 = blockIdx.x * TN;
    int tid = threadIdx.x;
    int lane = tid & 31;
    int wm = (tid >> 5) & 1, wn = tid >> 6;
    uint32_t ab = smem_u32(smem) + SOFF;
    int* rowpr = (int*)smem;
    __shared__ int s_base;
    if (tid < TM) {
        int m = m0 + tid;
        rowpr[tid] = (m < cnt) ? g_list[e][m] : -1;
    }
    if (tid == 0) s_base = expert_off(e) + m0;
    __syncthreads();

    const __half* Bp = g_W1t + ((size_t)e*NH + (size_t)n0)*ND;
    const int T = ND / KC;  // 16

    float acc[4][4][4];
    #pragma unroll
    for (int a = 0; a < 4; a++)
        #pragma unroll
        for (int b = 0; b < 4; b++)
            #pragma unroll
            for (int c = 0; c < 4; c++) acc[a][b][c] = 0.f;

    for (int s = 0; s < NSTG; s++) g1_load(ab, s, Bp, rowpr, tid);

    for (int t = 0; t < T; t++) {
        int buf = t % NSTG;
        if (t + NSTG <= T) CP_WAIT2(); else CP_WAIT0();
        __syncthreads();
        chunk_mma(ab, buf, wm, wn, lane, acc);
        __syncthreads();
        if (t + NSTG < T) g1_load(ab, t + NSTG, Bp, rowpr, tid);
    }

    int base_m = s_base;
    const float* bb = b1 + (size_t)e*NH + n0;
    #pragma unroll
    for (int mt = 0; mt < 4; mt++) {
        int r0 = wm*64 + mt*16 + (lane >> 2);
        #pragma unroll
        for (int half = 0; half < 2; half++) {
            int r = r0 + half*8;
            int pr = rowpr[r];
            if (pr < 0) continue;
            __half* hp = g_h + (size_t)(base_m + r)*NH + n0;
            #pragma unroll
            for (int nt = 0; nt < 4; nt++) {
                int cc = wn*32 + nt*8 + 2*(lane & 3);
                float v0 = acc[mt][nt][half*2+0] + bb[cc];
                float v1 = acc[mt][nt][half*2+1] + bb[cc+1];
                __half2 o = __floats2half2_rn(v0 * normcdff(v0), v1 * normcdff(v1));
                *(__half2*)(hp + cc) = o;
            }
        }
    }
}

// ---------------- GEMM2 (fused gating + combine): out += gate * (h @ W2 + b2) ----
__global__ __launch_bounds__(256, 2) void gemm2_mma(const float* __restrict__ b2,
                                                    float* __restrict__ out) {
    extern __shared__ char smem[];
    int e = blockIdx.z;
    int cnt = g_cnt[e];
    int m0 = blockIdx.y * TM;
    if (m0 >= cnt) return;
    int n0 = blockIdx.x * TN;
    int tid = threadIdx.x;
    int lane = tid & 31;
    int wm = (tid >> 5) & 1, wn = tid >> 6;
    uint32_t ab = smem_u32(smem) + SOFF;
    int* rowpr = (int*)smem;
    __shared__ int s_base;
    if (tid < TM) {
        int m = m0 + tid;
        rowpr[tid] = (m < cnt) ? g_list[e][m] : -1;
    }
    if (tid == 0) s_base = expert_off(e) + m0;
    __syncthreads();

    int base_m = s_base;
    int nvalid = cnt - m0; if (nvalid > TM) nvalid = TM;
    const __half* Bp = g_W2t + ((size_t)e*ND + (size_t)n0)*NH;
    const int T = NH / KC;  // 64

    float acc[4][4][4];
    #pragma unroll
    for (int a = 0; a < 4; a++)
        #pragma unroll
        for (int b = 0; b < 4; b++)
            #pragma unroll
            for (int c = 0; c < 4; c++) acc[a][b][c] = 0.f;

    for (int s = 0; s < NSTG; s++) g2_load(ab, s, base_m, nvalid, Bp, tid);

    for (int t = 0; t < T; t++) {
        int buf = t % NSTG;
        if (t + NSTG <= T) CP_WAIT2(); else CP_WAIT0();
        __syncthreads();
        chunk_mma(ab, buf, wm, wn, lane, acc);
        __syncthreads();
        if (t + NSTG < T) g2_load(ab, t + NSTG, base_m, nvalid, Bp, tid);
    }

    const float* bb = b2 + (size_t)e*ND + n0;
    #pragma unroll
    for (int mt = 0; mt < 4; mt++) {
        int r0 = wm*64 + mt*16 + (lane >> 2);
        #pragma unroll
        for (int half = 0; half < 2; half++) {
            int r = r0 + half*8;
            int pr = rowpr[r];
            if (pr < 0) continue;
            float g = g_gate[pr];
            float* op = out + (size_t)(pr >> 1)*ND + n0;
            #pragma unroll
            for (int nt = 0; nt < 4; nt++) {
                int cc = wn*32 + nt*8 + 2*(lane & 3);
                atomicAdd(op + cc,     g * (acc[mt][nt][half*2+0] + bb[cc]));
                atomicAdd(op + cc + 1, g * (acc[mt][nt][half*2+1] + bb[cc+1]));
            }
        }
    }
}

// ---------------- finalize aux losses ----------------
__global__ void finalize_kernel(float* __restrict__ out) {
    const float invT = 1.f/(float)NTOK;
    float lb = 0.f;
    #pragma unroll
    for (int e = 0; e < NE; e++) {
        float im = g_imp[e]*invT - 1.f/NE;
        lb += im*im;
    }
    lb *= 1.f/NE;
    float rz  = g_rz  * invT;
    float ent = g_ent * invT;
    size_t o = (size_t)NTOK*ND;
    out[o+0] = lb;
    out[o+1] = rz;
    out[o+2] = ent;
    out[o+3] = lb + 0.001f*rz - 0.001f*ent;
}

// ---------------- launch ----------------
extern "C" void kernel_launch(void* const* d_in, const int* in_sizes, int n_in,
                              void* d_out, int out_size) {
    const float* x      = (const float*)d_in[0];
    const float* ctx    = (const float*)d_in[1];
    const float* qual   = (const float*)d_in[2];
    const float* rn_g   = (const float*)d_in[3];
    const float* rn_b   = (const float*)d_in[4];
    const float* cn_g   = (const float*)d_in[5];
    const float* cn_b   = (const float*)d_in[6];
    const float* ctx_W  = (const float*)d_in[7];
    const float* ctx_b  = (const float*)d_in[8];
    const float* q_W    = (const float*)d_in[9];
    const float* q_b    = (const float*)d_in[10];
    const float* r_W    = (const float*)d_in[11];
    const float* r_b    = (const float*)d_in[12];
    const float* temp   = (const float*)d_in[13];
    const float* W1     = (const float*)d_in[14];
    const float* b1     = (const float*)d_in[15];
    const float* W2     = (const float*)d_in[16];
    const float* b2     = (const float*)d_in[17];
    float* out = (float*)d_out;

    cudaFuncSetAttribute(gemm1_mma, cudaFuncAttributeMaxDynamicSharedMemorySize, DSMEM);
    cudaFuncSetAttribute(gemm2_mma, cudaFuncAttributeMaxDynamicSharedMemorySize, DSMEM);

    prep_fused<<<PREP_BLKS + T1_BLKS + T2_BLKS, 256>>>(ctx_W, r_W, ctx_b, q_W,
                                                       q_b, r_b, W1, W2);    // 1
    router_kernel<<<NTOK/8, 256>>>(x, ctx, qual, rn_g, rn_b, cn_g, cn_b,
                                   r_W, temp, out);                          // 2
    gemm1_mma<<<dim3(NH/TN, NPAIR/TM, NE), 256, DSMEM>>>(b1);                // 3
    gemm2_mma<<<dim3(ND/TN, NPAIR/TM, NE), 256, DSMEM>>>(b2, out);           // 4 <- profiled
    finalize_kernel<<<1, 1>>>(out);                                          // 5
}

// round 15
// speedup vs baseline: 1.2172x; 1.0124x over previous
#include <cuda_runtime.h>
#include <cuda_fp16.h>
#include <math.h>
#include <stdint.h>

#define NB 4
#define NS 2048
#define ND 1024
#define NH 4096
#define NE 8
#define NTOK (NB*NS)      /* 8192 tokens */
#define NPAIR (NTOK*2)    /* 16384 (token,expert) pairs */

#define TM 128
#define TN 128
#define KC 64               /* K per stage (64 halfs = 128 B rows) */
#define NSTG 3
#define ROWB 144            /* padded row: 128 B data + 16 B pad */
#define ABYTES (128*ROWB)   /* 18432 B per matrix per stage */
#define STGB (2*ABYTES)
#define SOFF 512
#define DSMEM (SOFF + NSTG*STGB)   /* 111104 B -> 2 CTAs/SM */

// ---------------- device scratch (static allocations only) ----------------
__device__ float g_M[ND*NE];
__device__ float g_cvec[NE];
__device__ float g_qv[NE];
__device__ int   g_cnt[NE];
__device__ int   g_list[NE][NTOK];
__device__ float g_gate[NPAIR];
__device__ __half g_xh[(size_t)NTOK*ND];      // fp16 x (written by router)
__device__ __half g_W1t[(size_t)NE*NH*ND];    // W1^T  [e][n][k], fp16
__device__ __half g_W2t[(size_t)NE*ND*NH];    // W2^T  [e][n][k], fp16
__device__ __half g_h[(size_t)NPAIR*NH];      // hidden acts, fp16
__device__ float g_imp[NE];
__device__ float g_rz;
__device__ float g_ent;

// ---------------- helpers ----------------
__device__ __forceinline__ uint32_t smem_u32(const void* p) {
    uint32_t a;
    asm("{ .reg .u64 t; cvta.to.shared.u64 t, %1; cvt.u32.u64 %0, t; }"
        : "=r"(a) : "l"(p));
    return a;
}
__device__ __forceinline__ void cp16(uint32_t dst, const void* src, uint32_t bytes) {
    asm volatile("cp.async.cg.shared.global [%0], [%1], 16, %2;\n"
                 :: "r"(dst), "l"(src), "r"(bytes) : "memory");
}
#define CP_COMMIT() asm volatile("cp.async.commit_group;\n" ::: "memory")
#define CP_WAIT1()  asm volatile("cp.async.wait_group 1;\n" ::: "memory")
#define CP_WAIT0()  asm volatile("cp.async.wait_group 0;\n" ::: "memory")

__device__ __forceinline__ void mma_f16(float* c, const uint32_t* a, const uint32_t* b) {
    asm volatile("mma.sync.aligned.m16n8k16.row.col.f32.f16.f16.f32 "
        "{%0,%1,%2,%3}, {%4,%5,%6,%7}, {%8,%9}, {%0,%1,%2,%3};"
        : "+f"(c[0]), "+f"(c[1]), "+f"(c[2]), "+f"(c[3])
        : "r"(a[0]), "r"(a[1]), "r"(a[2]), "r"(a[3]), "r"(b[0]), "r"(b[1]));
}
__device__ __forceinline__ void ldsm4(uint32_t* r, uint32_t a) {
    asm volatile("ldmatrix.sync.aligned.m8n8.x4.shared.b16 {%0,%1,%2,%3}, [%4];"
        : "=r"(r[0]), "=r"(r[1]), "=r"(r[2]), "=r"(r[3]) : "r"(a));
}

// ---------------- prep: init + small vectors + prep_M + W1 transpose ----------
__device__ __forceinline__ float blk_sum(float v, float* sred) {
    int tid = threadIdx.x;
    sred[tid] = v;
    __syncthreads();
    #pragma unroll
    for (int o = 128; o > 0; o >>= 1) {
        if (tid < o) sred[tid] += sred[tid + o];
        __syncthreads();
    }
    float r = sred[0];
    __syncthreads();
    return r;
}

#define PREP_BLKS (ND+1)
#define T1_BLKS (NE*(ND/64)*(NH/32))   /* 16384 */
#define T2_BLKS (NE*(NH/64)*(ND/32))   /* 16384 */

// 64 S-rows x 32 S-cols transpose tile; D rows written as 128 B half2 runs.
__device__ __forceinline__ void transpose_tile(const float* S, __half* D,
                                               int R, int C, int r0, int c0,
                                               int tid) {
    __shared__ float t[64][33];
    int lane = tid & 31, w = tid >> 5;
    #pragma unroll
    for (int i = 0; i < 8; i++)
        t[w*8 + i][lane] = S[(size_t)(r0 + w*8 + i)*C + c0 + lane];
    __syncthreads();
    #pragma unroll
    for (int jj = 0; jj < 4; jj++) {
        int j = w + jj*8;
        __half2 v = __floats2half2_rn(t[2*lane][j], t[2*lane + 1][j]);
        *(__half2*)(D + (size_t)(c0 + j)*R + r0 + 2*lane) = v;
    }
}

__global__ __launch_bounds__(256) void prep_fused(
        const float* __restrict__ ctx_W, const float* __restrict__ r_W,
        const float* __restrict__ ctx_b, const float* __restrict__ q_W,
        const float* __restrict__ q_b,  const float* __restrict__ r_b,
        const float* __restrict__ W1) {
    int b = blockIdx.x;
    int tid = threadIdx.x;
    if (b < PREP_BLKS) {
        __shared__ float sred[256];
        if (b == 0) {
            if (tid < NE) { g_cnt[tid] = 0; g_imp[tid] = 0.f; }
            if (tid == 0) { g_rz = 0.f; g_ent = 0.f; }
            float pc[NE], pq[NE];
            #pragma unroll
            for (int e = 0; e < NE; e++) { pc[e] = 0.f; pq[e] = 0.f; }
            for (int d = tid; d < ND; d += 256) {
                float cb = ctx_b[d] + q_b[d];
                float qw = q_W[d];
                #pragma unroll
                for (int e = 0; e < NE; e++) {
                    pc[e] += cb * r_W[d*NE + e];
                    pq[e] += qw * r_W[d*NE + e];
                }
            }
            #pragma unroll
            for (int e = 0; e < NE; e++) {
                float vc = blk_sum(pc[e], sred);
                float vq = blk_sum(pq[e], sred);
                if (tid == 0) { g_cvec[e] = vc + r_b[e]; g_qv[e] = vq; }
            }
        } else {
            int j = b - 1;
            float part[NE];
            #pragma unroll
            for (int e = 0; e < NE; e++) part[e] = 0.f;
            for (int d = tid; d < ND; d += 256) {
                float w = ctx_W[(size_t)j*ND + d];
                #pragma unroll
                for (int e = 0; e < NE; e++) part[e] += w * r_W[d*NE + e];
            }
            #pragma unroll
            for (int e = 0; e < NE; e++) {
                float v = blk_sum(part[e], sred);
                if (tid == 0) g_M[j*NE + e] = v;
            }
        }
        return;
    }
    int i = b - PREP_BLKS;
    int e = i >> 11;            // / 2048
    int rem = i & 2047;         // 128 cblk x 16 rblk (R=ND=1024, C=NH)
    int c0 = (rem & 127) * 32;
    int r0 = (rem >> 7) * 64;
    transpose_tile(W1 + (size_t)e*ND*NH, g_W1t + (size_t)e*ND*NH,
                   ND, NH, r0, c0, tid);
}

// ---------------- W2 transpose (separate: runs after gemm1, profiled) --------
__global__ __launch_bounds__(256) void transpose_w2(const float* __restrict__ W2) {
    int i = blockIdx.x;
    int e = i >> 11;
    int rem = i & 2047;         // 32 cblk x 64 rblk (R=NH=4096, C=ND)
    int c0 = (rem & 31) * 32;
    int r0 = (rem >> 5) * 64;
    transpose_tile(W2 + (size_t)e*NH*ND, g_W2t + (size_t)e*NH*ND,
                   NH, ND, r0, c0, threadIdx.x);
}

// ---------------- router: one warp per token; also zeroes out[] ----------------
__global__ __launch_bounds__(256) void router_kernel(
        const float* __restrict__ x, const float* __restrict__ ctx,
        const float* __restrict__ quality,
        const float* __restrict__ rn_g, const float* __restrict__ rn_b,
        const float* __restrict__ cn_g, const float* __restrict__ cn_b,
        const float* __restrict__ r_W, const float* __restrict__ temp_p,
        float* __restrict__ out) {
    int wid = threadIdx.x >> 5, lane = threadIdx.x & 31;
    int t = blockIdx.x*8 + wid;

    {
        float4 z = make_float4(0.f,0.f,0.f,0.f);
        float4* op = (float4*)(out + (size_t)t*ND);
        #pragma unroll
        for (int i = 0; i < 8; i++) op[lane + 32*i] = z;
    }

    const float4* xr = (const float4*)(x   + (size_t)t*ND);
    const float4* cr = (const float4*)(ctx + (size_t)t*ND);
    float4 xv[8], cv[8];
    #pragma unroll
    for (int i = 0; i < 8; i++) { xv[i] = xr[lane + 32*i]; cv[i] = cr[lane + 32*i]; }

    #pragma unroll
    for (int i = 0; i < 8; i++) {
        __half2 h0 = __floats2half2_rn(xv[i].x, xv[i].y);
        __half2 h1 = __floats2half2_rn(xv[i].z, xv[i].w);
        uint2 o = make_uint2(*(uint32_t*)&h0, *(uint32_t*)&h1);
        *(uint2*)(g_xh + (size_t)t*ND + (lane + 32*i)*4) = o;
    }

    float sx=0.f, sxx=0.f, sc=0.f, scc=0.f;
    #pragma unroll
    for (int i = 0; i < 8; i++) {
        sx  += xv[i].x + xv[i].y + xv[i].z + xv[i].w;
        sxx += xv[i].x*xv[i].x + xv[i].y*xv[i].y + xv[i].z*xv[i].z + xv[i].w*xv[i].w;
        sc  += cv[i].x + cv[i].y + cv[i].z + cv[i].w;
        scc += cv[i].x*cv[i].x + cv[i].y*cv[i].y + cv[i].z*cv[i].z + cv[i].w*cv[i].w;
    }
    #pragma unroll
    for (int o = 16; o; o >>= 1) {
        sx  += __shfl_xor_sync(0xFFFFFFFFu, sx,  o);
        sxx += __shfl_xor_sync(0xFFFFFFFFu, sxx, o);
        sc  += __shfl_xor_sync(0xFFFFFFFFu, sc,  o);
        scc += __shfl_xor_sync(0xFFFFFFFFu, scc, o);
    }
    float mu_x = sx*(1.f/ND), mu_c = sc*(1.f/ND);
    float rs_x = rsqrtf(sxx*(1.f/ND) - mu_x*mu_x + 1e-5f);
    float rs_c = rsqrtf(scc*(1.f/ND) - mu_c*mu_c + 1e-5f);

    float part[NE];
    #pragma unroll
    for (int e = 0; e < NE; e++) part[e] = 0.f;
    #pragma unroll
    for (int i = 0; i < 8; i++) {
        float xa[4] = {xv[i].x, xv[i].y, xv[i].z, xv[i].w};
        float ca[4] = {cv[i].x, cv[i].y, cv[i].z, cv[i].w};
        #pragma unroll
        for (int j = 0; j < 4; j++) {
            int d = (lane + 32*i)*4 + j;
            float nx = (xa[j]-mu_x)*rs_x*rn_g[d] + rn_b[d];
            float nc = (ca[j]-mu_c)*rs_c*cn_g[d] + cn_b[d];
            const float* rw = r_W + d*NE;
            const float* mm = g_M + d*NE;
            #pragma unroll
            for (int e = 0; e < NE; e++) part[e] += nx*rw[e] + nc*mm[e];
        }
    }
    #pragma unroll
    for (int e = 0; e < NE; e++)
        #pragma unroll
        for (int o = 16; o; o >>= 1)
            part[e] += __shfl_xor_sync(0xFFFFFFFFu, part[e], o);

    __shared__ float simp[8][NE];
    __shared__ float srz[8];
    __shared__ float sent[8];

    if (lane == 0) {
        float temp = fmaxf(temp_p[0], 0.25f);
        float q = quality[t / NS];
        float lg[NE];
        #pragma unroll
        for (int e = 0; e < NE; e++)
            lg[e] = (part[e] + g_cvec[e] + q*g_qv[e]) / temp;

        int i1 = 0;
        #pragma unroll
        for (int e = 1; e < NE; e++) if (lg[e] > lg[i1]) i1 = e;
        int i2 = (i1 == 0) ? 1 : 0;
        #pragma unroll
        for (int e = 0; e < NE; e++) {
            if (e == i1 || e == i2) continue;
            if (lg[e] > lg[i2]) i2 = e;
        }

        float mx = lg[0];
        #pragma unroll
        for (int e = 1; e < NE; e++) mx = fmaxf(mx, lg[e]);
        float se = 0.f;
        #pragma unroll
        for (int e = 0; e < NE; e++) se += expf(lg[e]-mx);
        float lse = mx + logf(se);
        float inv_se = 1.f/se;
        float ent = 0.f;
        #pragma unroll
        for (int e = 0; e < NE; e++) {
            float p = expf(lg[e]-mx)*inv_se;
            simp[wid][e] = p;
            ent -= p * (lg[e]-lse);
        }
        srz[wid]  = lse*lse;
        sent[wid] = ent;

        float ex = expf(lg[i2]-lg[i1]);
        float inv = 1.f/(1.f+ex);
        g_gate[2*t]   = inv;
        g_gate[2*t+1] = ex*inv;
        int p1 = atomicAdd(&g_cnt[i1], 1);
        g_list[i1][p1] = 2*t;
        int p2 = atomicAdd(&g_cnt[i2], 1);
        g_list[i2][p2] = 2*t+1;
    }
    __syncthreads();
    int tid = threadIdx.x;
    if (tid < NE) {
        float s = 0.f;
        #pragma unroll
        for (int w = 0; w < 8; w++) s += simp[w][tid];
        atomicAdd(&g_imp[tid], s);
    } else if (tid == 8) {
        float s = 0.f;
        #pragma unroll
        for (int w = 0; w < 8; w++) s += srz[w];
        atomicAdd(&g_rz, s);
    } else if (tid == 9) {
        float s = 0.f;
        #pragma unroll
        for (int w = 0; w < 8; w++) s += sent[w];
        atomicAdd(&g_ent, s);
    }
}

// ---------------- stage loaders (fp16 rows: 128 B data + 16 B pad) ----------------
__device__ __forceinline__ void g1_load(uint32_t ab, int s,
        const __half* __restrict__ Bp, const int* rowpr, int tid) {
    int buf = s % NSTG;
    int k0 = s * KC;
    uint32_t abase = ab + buf*STGB;
    uint32_t bbase = abase + ABYTES;
    #pragma unroll
    for (int i = 0; i < 4; i++) {
        int u = tid + 256*i; int r = u >> 3, sj = u & 7;
        int pr = rowpr[r];
        const __half* src = (pr >= 0) ? (g_xh + ((size_t)(pr >> 1))*ND + k0 + sj*8) : g_xh;
        cp16(abase + r*ROWB + sj*16, src, (pr >= 0) ? 16u : 0u);
    }
    #pragma unroll
    for (int i = 0; i < 4; i++) {
        int u = tid + 256*i; int r = u >> 3, sj = u & 7;
        cp16(bbase + r*ROWB + sj*16, Bp + (size_t)r*ND + k0 + sj*8, 16u);
    }
    CP_COMMIT();
}

__device__ __forceinline__ void g2_load(uint32_t ab, int s,
        int base_m, int nvalid, const __half* __restrict__ Bp, int tid) {
    int buf = s % NSTG;
    int k0 = s * KC;
    uint32_t abase = ab + buf*STGB;
    uint32_t bbase = abase + ABYTES;
    #pragma unroll
    for (int i = 0; i < 4; i++) {
        int u = tid + 256*i; int r = u >> 3, sj = u & 7;
        bool ok = (r < nvalid);
        const __half* src = g_h + (size_t)(base_m + (ok ? r : 0))*NH + k0 + sj*8;
        cp16(abase + r*ROWB + sj*16, src, ok ? 16u : 0u);
    }
    #pragma unroll
    for (int i = 0; i < 4; i++) {
        int u = tid + 256*i; int r = u >> 3, sj = u & 7;
        cp16(bbase + r*ROWB + sj*16, Bp + (size_t)r*NH + k0 + sj*8, 16u);
    }
    CP_COMMIT();
}

// ---------------- fragment load for one k16-step ----------------
__device__ __forceinline__ void ldfrags(uint32_t As, uint32_t Bs, int ks,
        int arow, uint32_t acol, int brow, uint32_t bcol,
        uint32_t af[4][4], uint32_t bf[2][4]) {
    uint32_t kb = (uint32_t)(ks*32);
    #pragma unroll
    for (int mt = 0; mt < 4; mt++)
        ldsm4(af[mt], As + (uint32_t)(arow + mt*16)*ROWB + kb + acol);
    #pragma unroll
    for (int p = 0; p < 2; p++)
        ldsm4(bf[p], Bs + (uint32_t)(brow + p*16)*ROWB + kb + bcol);
}

// ---------------- chunk compute: register double-buffered fragments ----------------
__device__ __forceinline__ void chunk_mma(uint32_t ab, int buf,
        int wm, int wn, int lane, float acc[4][4][4]) {
    uint32_t As = ab + buf*STGB;
    uint32_t Bs = As + ABYTES;
    int l7 = lane & 7;
    int arow = wm*64 + ((lane>>3)&1)*8 + l7;
    uint32_t acol = (uint32_t)((lane>>4)*16);
    int brow = wn*32 + ((lane>>4)&1)*8 + l7;
    uint32_t bcol = (uint32_t)(((lane>>3)&1)*16);

    uint32_t af[2][4][4], bf[2][2][4];
    ldfrags(As, Bs, 0, arow, acol, brow, bcol, af[0], bf[0]);
    #pragma unroll
    for (int ks = 0; ks < 4; ks++) {
        int cur = ks & 1, nxt = cur ^ 1;
        if (ks < 3)
            ldfrags(As, Bs, ks+1, arow, acol, brow, bcol, af[nxt], bf[nxt]);
        #pragma unroll
        for (int mt = 0; mt < 4; mt++)
            #pragma unroll
            for (int nt = 0; nt < 4; nt++)
                mma_f16(acc[mt][nt], af[cur][mt], &bf[cur][nt>>1][(nt&1)*2]);
    }
}

// ---------------- expert offset ----------------
__device__ __forceinline__ int expert_off(int e) {
    int s = 0;
    #pragma unroll
    for (int k = 0; k < NE; k++) if (k < e) s += g_cnt[k];
    return s;
}

// ---------------- GEMM1: h = h16(gelu(x @ W1 + b1)) ----------------
__global__ __launch_bounds__(256, 2) void gemm1_mma(const float* __restrict__ b1) {
    extern __shared__ char smem[];
    int e = blockIdx.z;
    int cnt = g_cnt[e];
    int m0 = blockIdx.y * TM;
    if (m0 >= cnt) return;
    int n0 = blockIdx.x * TN;
    int tid = threadIdx.x;
    int lane = tid & 31;
    int wm = (tid >> 5) & 1, wn = tid >> 6;
    uint32_t ab = smem_u32(smem) + SOFF;
    int* rowpr = (int*)smem;
    __shared__ int s_base;
    if (tid < TM) {
        int m = m0 + tid;
        rowpr[tid] = (m < cnt) ? g_list[e][m] : -1;
    }
    if (tid == 0) s_base = expert_off(e) + m0;
    __syncthreads();

    const __half* Bp = g_W1t + ((size_t)e*NH + (size_t)n0)*ND;
    const int T = ND / KC;  // 16

    float acc[4][4][4];
    #pragma unroll
    for (int a = 0; a < 4; a++)
        #pragma unroll
        for (int b = 0; b < 4; b++)
            #pragma unroll
            for (int c = 0; c < 4; c++) acc[a][b][c] = 0.f;

    // single-barrier multistage: prologue loads stages 0..NSTG-2
    for (int s = 0; s < NSTG-1; s++) g1_load(ab, s, Bp, rowpr, tid);

    for (int t = 0; t < T; t++) {
        if (t < T-1) CP_WAIT1(); else CP_WAIT0();
        __syncthreads();
        if (t + NSTG - 1 < T) g1_load(ab, t + NSTG - 1, Bp, rowpr, tid);
        chunk_mma(ab, t % NSTG, wm, wn, lane, acc);
    }

    int base_m = s_base;
    const float* bb = b1 + (size_t)e*NH + n0;
    #pragma unroll
    for (int mt = 0; mt < 4; mt++) {
        int r0 = wm*64 + mt*16 + (lane >> 2);
        #pragma unroll
        for (int half = 0; half < 2; half++) {
            int r = r0 + half*8;
            int pr = rowpr[r];
            if (pr < 0) continue;
            __half* hp = g_h + (size_t)(base_m + r)*NH + n0;
            #pragma unroll
            for (int nt = 0; nt < 4; nt++) {
                int cc = wn*32 + nt*8 + 2*(lane & 3);
                float v0 = acc[mt][nt][half*2+0] + bb[cc];
                float v1 = acc[mt][nt][half*2+1] + bb[cc+1];
                __half2 o = __floats2half2_rn(v0 * normcdff(v0), v1 * normcdff(v1));
                *(__half2*)(hp + cc) = o;
            }
        }
    }
}

// ---------------- GEMM2 (fused gating + combine): out += gate * (h @ W2 + b2) ----
__global__ __launch_bounds__(256, 2) void gemm2_mma(const float* __restrict__ b2,
                                                    float* __restrict__ out) {
    extern __shared__ char smem[];
    int e = blockIdx.z;
    int cnt = g_cnt[e];
    int m0 = blockIdx.y * TM;
    if (m0 >= cnt) return;
    int n0 = blockIdx.x * TN;
    int tid = threadIdx.x;
    int lane = tid & 31;
    int wm = (tid >> 5) & 1, wn = tid >> 6;
    uint32_t ab = smem_u32(smem) + SOFF;
    int* rowpr = (int*)smem;
    __shared__ int s_base;
    if (tid < TM) {
        int m = m0 + tid;
        rowpr[tid] = (m < cnt) ? g_list[e][m] : -1;
    }
    if (tid == 0) s_base = expert_off(e) + m0;
    __syncthreads();

    int base_m = s_base;
    int nvalid = cnt - m0; if (nvalid > TM) nvalid = TM;
    const __half* Bp = g_W2t + ((size_t)e*ND + (size_t)n0)*NH;
    const int T = NH / KC;  // 64

    float acc[4][4][4];
    #pragma unroll
    for (int a = 0; a < 4; a++)
        #pragma unroll
        for (int b = 0; b < 4; b++)
            #pragma unroll
            for (int c = 0; c < 4; c++) acc[a][b][c] = 0.f;

    for (int s = 0; s < NSTG-1; s++) g2_load(ab, s, base_m, nvalid, Bp, tid);

    for (int t = 0; t < T; t++) {
        if (t < T-1) CP_WAIT1(); else CP_WAIT0();
        __syncthreads();
        if (t + NSTG - 1 < T) g2_load(ab, t + NSTG - 1, base_m, nvalid, Bp, tid);
        chunk_mma(ab, t % NSTG, wm, wn, lane, acc);
    }

    const float* bb = b2 + (size_t)e*ND + n0;
    #pragma unroll
    for (int mt = 0; mt < 4; mt++) {
        int r0 = wm*64 + mt*16 + (lane >> 2);
        #pragma unroll
        for (int half = 0; half < 2; half++) {
            int r = r0 + half*8;
            int pr = rowpr[r];
            if (pr < 0) continue;
            float g = g_gate[pr];
            float* op = out + (size_t)(pr >> 1)*ND + n0;
            #pragma unroll
            for (int nt = 0; nt < 4; nt++) {
                int cc = wn*32 + nt*8 + 2*(lane & 3);
                atomicAdd(op + cc,     g * (acc[mt][nt][half*2+0] + bb[cc]));
                atomicAdd(op + cc + 1, g * (acc[mt][nt][half*2+1] + bb[cc+1]));
            }
        }
    }
}

// ---------------- finalize aux losses ----------------
__global__ void finalize_kernel(float* __restrict__ out) {
    const float invT = 1.f/(float)NTOK;
    float lb = 0.f;
    #pragma unroll
    for (int e = 0; e < NE; e++) {
        float im = g_imp[e]*invT - 1.f/NE;
        lb += im*im;
    }
    lb *= 1.f/NE;
    float rz  = g_rz  * invT;
    float ent = g_ent * invT;
    size_t o = (size_t)NTOK*ND;
    out[o+0] = lb;
    out[o+1] = rz;
    out[o+2] = ent;
    out[o+3] = lb + 0.001f*rz - 0.001f*ent;
}

// ---------------- launch ----------------
extern "C" void kernel_launch(void* const* d_in, const int* in_sizes, int n_in,
                              void* d_out, int out_size) {
    const float* x      = (const float*)d_in[0];
    const float* ctx    = (const float*)d_in[1];
    const float* qual   = (const float*)d_in[2];
    const float* rn_g   = (const float*)d_in[3];
    const float* rn_b   = (const float*)d_in[4];
    const float* cn_g   = (const float*)d_in[5];
    const float* cn_b   = (const float*)d_in[6];
    const float* ctx_W  = (const float*)d_in[7];
    const float* ctx_b  = (const float*)d_in[8];
    const float* q_W    = (const float*)d_in[9];
    const float* q_b    = (const float*)d_in[10];
    const float* r_W    = (const float*)d_in[11];
    const float* r_b    = (const float*)d_in[12];
    const float* temp   = (const float*)d_in[13];
    const float* W1     = (const float*)d_in[14];
    const float* b1     = (const float*)d_in[15];
    const float* W2     = (const float*)d_in[16];
    const float* b2     = (const float*)d_in[17];
    float* out = (float*)d_out;

    cudaFuncSetAttribute(gemm1_mma, cudaFuncAttributeMaxDynamicSharedMemorySize, DSMEM);
    cudaFuncSetAttribute(gemm2_mma, cudaFuncAttributeMaxDynamicSharedMemorySize, DSMEM);

    // our 4th launch is profiled -> transpose_w2 this round (instrumentation)
    prep_fused<<<PREP_BLKS + T1_BLKS, 256>>>(ctx_W, r_W, ctx_b, q_W,
                                             q_b, r_b, W1);               // 1
    router_kernel<<<NTOK/8, 256>>>(x, ctx, qual, rn_g, rn_b, cn_g, cn_b,
                                   r_W, temp, out);                       // 2
    gemm1_mma<<<dim3(NH/TN, NPAIR/TM, NE), 256, DSMEM>>>(b1);             // 3
    transpose_w2<<<T2_BLKS, 256>>>(W2);                                   // 4 <- profiled
    gemm2_mma<<<dim3(ND/TN, NPAIR/TM, NE), 256, DSMEM>>>(b2, out);        // 5
    finalize_kernel<<<1, 1>>>(out);                                       // 6
}